// round 1
// baseline (speedup 1.0000x reference)
#include <cuda_runtime.h>

// Problem dims
#define BB 2
#define TT 1024
#define DD 768
#define HH 12
#define HSZ 64
#define EE 8
#define DFF 3072
#define NN 2048           // B*T tokens
#define NPAD 2560         // NN + EE*64 (tile-aligned expert segments)

// ---------------- scratch (device globals; no allocations allowed) -------------
__device__ float g_h[NN * DD];        // ln1 output
__device__ float g_q[NN * DD];        // [B,H,T,HS]
__device__ float g_k[NN * DD];
__device__ float g_v[NN * DD];
__device__ float g_att[NN * DD];      // attention out, [B,T,D] concat-head
__device__ float g_h2[NN * DD];       // ln2 output
__device__ float g_hid[NPAD * DFF];   // expert hidden (relu)
__device__ int   g_sel[NN];
__device__ int   g_cnt[EE];
__device__ int   g_cur[EE];
__device__ int   g_off[EE + 1];       // padded (64-aligned) segment offsets
__device__ int   g_perm[NPAD];

// ---------------- LayerNorm ----------------------------------------------------
// one block (256 thr) per row of 768
__global__ void ln_kernel(const float* __restrict__ x, const float* __restrict__ gw,
                          const float* __restrict__ gb, int which) {
    float* out = which ? g_h2 : g_h;
    int row = blockIdx.x, tid = threadIdx.x;
    const float* xp = x + row * DD;
    float v0 = xp[tid], v1 = xp[tid + 256], v2 = xp[tid + 512];
    float s = v0 + v1 + v2;
    float s2 = v0 * v0 + v1 * v1 + v2 * v2;
#pragma unroll
    for (int o = 16; o; o >>= 1) {
        s  += __shfl_xor_sync(0xffffffffu, s, o);
        s2 += __shfl_xor_sync(0xffffffffu, s2, o);
    }
    __shared__ float r1[8], r2[8];
    if ((tid & 31) == 0) { r1[tid >> 5] = s; r2[tid >> 5] = s2; }
    __syncthreads();
    s = 0.f; s2 = 0.f;
#pragma unroll
    for (int i = 0; i < 8; i++) { s += r1[i]; s2 += r2[i]; }
    float mu = s * (1.f / DD);
    float var = s2 * (1.f / DD) - mu * mu;
    float rs = rsqrtf(var + 1e-5f);
    float* op = out + row * DD;
    op[tid]       = (v0 - mu) * rs * gw[tid]       + gb[tid];
    op[tid + 256] = (v1 - mu) * rs * gw[tid + 256] + gb[tid + 256];
    op[tid + 512] = (v2 - mu) * rs * gw[tid + 512] + gb[tid + 512];
}

// ---------------- QKV projection: h[2048,768] x W{q,k,v}[H,768,64] -------------
// grid = (32 mtiles, 36); y selects matrix+head. Output layout [B,H,T,HS].
__global__ __launch_bounds__(256) void qkv_gemm(
    const float* __restrict__ Wq, const float* __restrict__ Wk, const float* __restrict__ Wv) {
    __shared__ float As[16][65];
    __shared__ float Bs[16][64];
    int tid = threadIdx.x;
    int m0 = blockIdx.x * 64;
    int y = blockIdx.y;
    const float* W; float* dst; int h;
    if (y < 12)      { W = Wq; dst = g_q; h = y; }
    else if (y < 24) { W = Wk; dst = g_k; h = y - 12; }
    else             { W = Wv; dst = g_v; h = y - 24; }
    const float* wb = W + h * DD * HSZ;
    int tx = tid & 15, ty = tid >> 4;
    float c[4][4] = {};
    for (int k0 = 0; k0 < DD; k0 += 16) {
#pragma unroll
        for (int i = 0; i < 4; i++) {
            int idx = tid + i * 256;
            int kk = idx & 15, mm = idx >> 4;
            As[kk][mm] = g_h[(m0 + mm) * DD + k0 + kk];
        }
#pragma unroll
        for (int i = 0; i < 4; i++) {
            int idx = tid + i * 256;
            int nn = idx & 63, kk = idx >> 6;
            Bs[kk][nn] = wb[(k0 + kk) * HSZ + nn];
        }
        __syncthreads();
#pragma unroll
        for (int kk = 0; kk < 16; kk++) {
            float a[4], b[4];
#pragma unroll
            for (int i = 0; i < 4; i++) a[i] = As[kk][ty * 4 + i];
#pragma unroll
            for (int j = 0; j < 4; j++) b[j] = Bs[kk][tx * 4 + j];
#pragma unroll
            for (int i = 0; i < 4; i++)
#pragma unroll
                for (int j = 0; j < 4; j++) c[i][j] += a[i] * b[j];
        }
        __syncthreads();
    }
#pragma unroll
    for (int i = 0; i < 4; i++) {
        int m = m0 + ty * 4 + i;
        int b_ = m >> 10, t = m & 1023;
        float* o = dst + (((b_ * HH) + h) * TT + t) * HSZ;
#pragma unroll
        for (int j = 0; j < 4; j++) o[tx * 4 + j] = c[i][j];
    }
}

// ---------------- causal attention (flash-style, fp32) -------------------------
// grid = (8 qtiles, H, B), 128 thr, 1 query/thread, 32-key tiles.
__global__ __launch_bounds__(128) void attn_kernel() {
    __shared__ float ksh[32][64];
    __shared__ float vsh[32][64];
    __shared__ float psh[128][33];
    int qt = blockIdx.x, h = blockIdx.y, b = blockIdx.z;
    int tid = threadIdx.x;
    int qi = qt * 128 + tid;
    const float scale = rsqrtf((float)DD);   // reference scales by n_embed^-0.5
    const float* qp = g_q + (((b * HH) + h) * TT + qi) * HSZ;
    float qreg[64];
#pragma unroll
    for (int d = 0; d < 64; d++) qreg[d] = qp[d] * scale;
    float acc[64];
#pragma unroll
    for (int d = 0; d < 64; d++) acc[d] = 0.f;
    float m = -1e30f, l = 0.f;
    int ntiles = (qt + 1) * 4;
    const float* kbase = g_k + ((b * HH) + h) * TT * HSZ;
    const float* vbase = g_v + ((b * HH) + h) * TT * HSZ;
    for (int kt = 0; kt < ntiles; kt++) {
        const float* kp = kbase + kt * 32 * 64;
        const float* vp = vbase + kt * 32 * 64;
#pragma unroll
        for (int i = 0; i < 16; i++) {
            int idx = tid + i * 128;
            ksh[idx >> 6][idx & 63] = kp[idx];
            vsh[idx >> 6][idx & 63] = vp[idx];
        }
        __syncthreads();
        float mt = m;
        for (int j = 0; j < 32; j++) {
            int key = kt * 32 + j;
            float s = -1e30f;
            if (key <= qi) {
                s = 0.f;
#pragma unroll
                for (int d = 0; d < 64; d++) s += qreg[d] * ksh[j][d];
            }
            psh[tid][j] = s;
            mt = fmaxf(mt, s);
        }
        float r = __expf(m - mt);
        l *= r;
#pragma unroll
        for (int d = 0; d < 64; d++) acc[d] *= r;
        float lsum = 0.f;
        for (int j = 0; j < 32; j++) {
            float p = __expf(psh[tid][j] - mt);
            lsum += p;
            psh[tid][j] = p;
        }
        l += lsum;
        for (int j = 0; j < 32; j++) {
            float p = psh[tid][j];
#pragma unroll
            for (int d = 0; d < 64; d++) acc[d] += p * vsh[j][d];
        }
        m = mt;
        __syncthreads();
    }
    float inv = 1.f / l;
    float* op = g_att + (b * TT + qi) * DD + h * HSZ;
#pragma unroll
    for (int d = 0; d < 64; d++) op[d] = acc[d] * inv;
}

// ---------------- output projection + residual: out = x + att@Wp + bp ----------
__global__ __launch_bounds__(256) void proj_gemm(
    const float* __restrict__ Wp, const float* __restrict__ bp,
    const float* __restrict__ x, float* __restrict__ out) {
    __shared__ float As[16][65];
    __shared__ float Bs[16][64];
    int tid = threadIdx.x;
    int m0 = blockIdx.x * 64;
    int n0 = blockIdx.y * 64;
    int tx = tid & 15, ty = tid >> 4;
    float c[4][4] = {};
    for (int k0 = 0; k0 < DD; k0 += 16) {
#pragma unroll
        for (int i = 0; i < 4; i++) {
            int idx = tid + i * 256;
            int kk = idx & 15, mm = idx >> 4;
            As[kk][mm] = g_att[(m0 + mm) * DD + k0 + kk];
        }
#pragma unroll
        for (int i = 0; i < 4; i++) {
            int idx = tid + i * 256;
            int nn = idx & 63, kk = idx >> 6;
            Bs[kk][nn] = Wp[(k0 + kk) * DD + n0 + nn];
        }
        __syncthreads();
#pragma unroll
        for (int kk = 0; kk < 16; kk++) {
            float a[4], b[4];
#pragma unroll
            for (int i = 0; i < 4; i++) a[i] = As[kk][ty * 4 + i];
#pragma unroll
            for (int j = 0; j < 4; j++) b[j] = Bs[kk][tx * 4 + j];
#pragma unroll
            for (int i = 0; i < 4; i++)
#pragma unroll
                for (int j = 0; j < 4; j++) c[i][j] += a[i] * b[j];
        }
        __syncthreads();
    }
#pragma unroll
    for (int i = 0; i < 4; i++) {
        int m = m0 + ty * 4 + i;
#pragma unroll
        for (int j = 0; j < 4; j++) {
            int jg = n0 + tx * 4 + j;
            out[m * DD + jg] = c[i][j] + bp[jg] + x[m * DD + jg];
        }
    }
}

// ---------------- MoE gate (top-1 == argmax, weight == 1.0 exactly) ------------
__global__ void gate_kernel(const float* __restrict__ Wg) {
    int gtid = blockIdx.x * blockDim.x + threadIdx.x;
    int warp = gtid >> 5, lane = gtid & 31;
    if (warp >= NN) return;
    const float* hp = g_h2 + warp * DD;
    float best = -1e30f; int bi = 0;
    for (int e = 0; e < EE; e++) {
        float s = 0.f;
        for (int i = lane; i < DD; i += 32) s += hp[i] * Wg[i * EE + e];
#pragma unroll
        for (int o = 16; o; o >>= 1) s += __shfl_xor_sync(0xffffffffu, s, o);
        if (s > best) { best = s; bi = e; }  // strict > keeps lowest index on ties (matches top_k)
    }
    if (lane == 0) g_sel[warp] = bi;
}

__global__ void moe_zero() { int t = threadIdx.x; if (t < EE) { g_cnt[t] = 0; g_cur[t] = 0; } }
__global__ void moe_count() {
    int n = blockIdx.x * 256 + threadIdx.x;
    if (n < NN) atomicAdd(&g_cnt[g_sel[n]], 1);
}
__global__ void moe_scan() {
    if (threadIdx.x == 0) {
        int o = 0;
        for (int e = 0; e < EE; e++) { g_off[e] = o; o += ((g_cnt[e] + 63) >> 6) << 6; }
        g_off[EE] = o;
    }
}
__global__ void moe_scatter() {
    int n = blockIdx.x * 256 + threadIdx.x;
    if (n < NN) {
        int e = g_sel[n];
        int p = atomicAdd(&g_cur[e], 1);
        g_perm[g_off[e] + p] = n;
    }
}

// ---------------- expert FFN1: hid = relu(h2[perm] @ W1[e] + b1[e]) ------------
__global__ __launch_bounds__(256) void ffn1_gemm(const float* __restrict__ W1,
                                                 const float* __restrict__ b1) {
    int row0 = blockIdx.x * 64;
    if (row0 >= g_off[EE]) return;
    int e = 0;
#pragma unroll
    for (int i = 1; i < EE; i++) if (row0 >= g_off[i]) e = i;
    int valid = g_cnt[e] - (row0 - g_off[e]);
    if (valid > 64) valid = 64;
    __shared__ int toks[64];
    __shared__ float As[16][65];
    __shared__ float Bs[16][64];
    int tid = threadIdx.x;
    if (tid < 64) toks[tid] = (tid < valid) ? g_perm[row0 + tid] : 0;
    __syncthreads();
    const float* wb = W1 + e * DD * DFF;
    int n0 = blockIdx.y * 64;
    int tx = tid & 15, ty = tid >> 4;
    float c[4][4] = {};
    for (int k0 = 0; k0 < DD; k0 += 16) {
#pragma unroll
        for (int i = 0; i < 4; i++) {
            int idx = tid + i * 256;
            int kk = idx & 15, mm = idx >> 4;
            As[kk][mm] = (mm < valid) ? g_h2[toks[mm] * DD + k0 + kk] : 0.f;
        }
#pragma unroll
        for (int i = 0; i < 4; i++) {
            int idx = tid + i * 256;
            int nn = idx & 63, kk = idx >> 6;
            Bs[kk][nn] = wb[(k0 + kk) * DFF + n0 + nn];
        }
        __syncthreads();
#pragma unroll
        for (int kk = 0; kk < 16; kk++) {
            float a[4], b[4];
#pragma unroll
            for (int i = 0; i < 4; i++) a[i] = As[kk][ty * 4 + i];
#pragma unroll
            for (int j = 0; j < 4; j++) b[j] = Bs[kk][tx * 4 + j];
#pragma unroll
            for (int i = 0; i < 4; i++)
#pragma unroll
                for (int j = 0; j < 4; j++) c[i][j] += a[i] * b[j];
        }
        __syncthreads();
    }
#pragma unroll
    for (int i = 0; i < 4; i++) {
        int mm = ty * 4 + i;
        if (mm < valid) {
#pragma unroll
            for (int j = 0; j < 4; j++) {
                int jg = n0 + tx * 4 + j;
                float v = c[i][j] + b1[e * DFF + jg];
                g_hid[(row0 + mm) * DFF + jg] = v > 0.f ? v : 0.f;
            }
        }
    }
}

// ---------------- expert FFN2: out[tok] += hid @ W2[e] + b2[e] -----------------
__global__ __launch_bounds__(256) void ffn2_gemm(const float* __restrict__ W2,
                                                 const float* __restrict__ b2,
                                                 float* __restrict__ out) {
    int row0 = blockIdx.x * 64;
    if (row0 >= g_off[EE]) return;
    int e = 0;
#pragma unroll
    for (int i = 1; i < EE; i++) if (row0 >= g_off[i]) e = i;
    int valid = g_cnt[e] - (row0 - g_off[e]);
    if (valid > 64) valid = 64;
    __shared__ int toks[64];
    __shared__ float As[16][65];
    __shared__ float Bs[16][64];
    int tid = threadIdx.x;
    if (tid < 64) toks[tid] = (tid < valid) ? g_perm[row0 + tid] : 0;
    __syncthreads();
    const float* wb = W2 + e * DFF * DD;
    int n0 = blockIdx.y * 64;
    int tx = tid & 15, ty = tid >> 4;
    float c[4][4] = {};
    for (int k0 = 0; k0 < DFF; k0 += 16) {
#pragma unroll
        for (int i = 0; i < 4; i++) {
            int idx = tid + i * 256;
            int kk = idx & 15, mm = idx >> 4;
            As[kk][mm] = (mm < valid) ? g_hid[(row0 + mm) * DFF + k0 + kk] : 0.f;
        }
#pragma unroll
        for (int i = 0; i < 4; i++) {
            int idx = tid + i * 256;
            int nn = idx & 63, kk = idx >> 6;
            Bs[kk][nn] = wb[(k0 + kk) * DD + n0 + nn];
        }
        __syncthreads();
#pragma unroll
        for (int kk = 0; kk < 16; kk++) {
            float a[4], b[4];
#pragma unroll
            for (int i = 0; i < 4; i++) a[i] = As[kk][ty * 4 + i];
#pragma unroll
            for (int j = 0; j < 4; j++) b[j] = Bs[kk][tx * 4 + j];
#pragma unroll
            for (int i = 0; i < 4; i++)
#pragma unroll
                for (int j = 0; j < 4; j++) c[i][j] += a[i] * b[j];
        }
        __syncthreads();
    }
#pragma unroll
    for (int i = 0; i < 4; i++) {
        int mm = ty * 4 + i;
        if (mm < valid) {
            int tok = toks[mm];
#pragma unroll
            for (int j = 0; j < 4; j++) {
                int jg = n0 + tx * 4 + j;
                out[tok * DD + jg] += c[i][j] + b2[e * DD + jg];
            }
        }
    }
}

// ---------------- launch -------------------------------------------------------
extern "C" void kernel_launch(void* const* d_in, const int* in_sizes, int n_in,
                              void* d_out, int out_size) {
    const float* x     = (const float*)d_in[0];
    const float* ln1_g = (const float*)d_in[1];
    const float* ln1_b = (const float*)d_in[2];
    const float* ln2_g = (const float*)d_in[3];
    const float* ln2_b = (const float*)d_in[4];
    const float* Wq    = (const float*)d_in[5];
    const float* Wk    = (const float*)d_in[6];
    const float* Wv    = (const float*)d_in[7];
    const float* Wp    = (const float*)d_in[8];
    const float* bp    = (const float*)d_in[9];
    const float* Wg    = (const float*)d_in[10];
    const float* W1    = (const float*)d_in[11];
    const float* b1    = (const float*)d_in[12];
    const float* W2    = (const float*)d_in[13];
    const float* b2    = (const float*)d_in[14];
    float* out = (float*)d_out;

    ln_kernel<<<NN, 256>>>(x, ln1_g, ln1_b, 0);
    qkv_gemm<<<dim3(NN / 64, 36), 256>>>(Wq, Wk, Wv);
    attn_kernel<<<dim3(TT / 128, HH, BB), 128>>>();
    proj_gemm<<<dim3(NN / 64, DD / 64), 256>>>(Wp, bp, x, out);
    ln_kernel<<<NN, 256>>>(out, ln2_g, ln2_b, 1);
    moe_zero<<<1, 32>>>();
    gate_kernel<<<NN * 32 / 256, 256>>>(Wg);
    moe_count<<<NN / 256, 256>>>();
    moe_scan<<<1, 1>>>();
    moe_scatter<<<NN / 256, 256>>>();
    ffn1_gemm<<<dim3(NPAD / 64, DFF / 64), 256>>>(W1, b1);
    ffn2_gemm<<<dim3(NPAD / 64, DD / 64), 256>>>(W2, b2, out);
}

// round 2
// speedup vs baseline: 1.8571x; 1.8571x over previous
#include <cuda_runtime.h>

// Problem dims
#define BB 2
#define TT 1024
#define DD 768
#define HH 12
#define HSZ 64
#define EE 8
#define DFF 3072
#define NN 2048           // B*T tokens
#define NPAD 3072         // NN + EE*128 (tile-aligned expert segments)

// ---------------- scratch (device globals; no allocations allowed) -------------
__device__ float g_h[NN * DD];        // ln1 output
__device__ float g_q[NN * DD];        // [B,H,T,HS]
__device__ float g_k[NN * DD];
__device__ float g_v[NN * DD];
__device__ float g_att[NN * DD];      // attention out, [B,T,D] concat-head
__device__ float g_h2[NN * DD];       // ln2 output
__device__ float g_hid[NPAD * DFF];   // expert hidden (relu); padded rows stay 0
__device__ int   g_sel[NN];
__device__ int   g_cnt[EE];
__device__ int   g_cur[EE];
__device__ int   g_off[EE + 1];       // padded (128-aligned) segment offsets
__device__ int   g_perm[NPAD];

// ---------------- tf32 helpers -------------------------------------------------
__device__ __forceinline__ unsigned f2tf(float v) {
    unsigned r;
    asm("cvt.rna.tf32.f32 %0, %1;" : "=r"(r) : "f"(v));
    return r;
}
__device__ __forceinline__ float f2tff(float v) { return __uint_as_float(f2tf(v)); }

__device__ __forceinline__ void mma8(float* c, const unsigned* a, const unsigned* b) {
    asm volatile(
        "mma.sync.aligned.m16n8k8.row.col.f32.tf32.tf32.f32 "
        "{%0,%1,%2,%3},{%4,%5,%6,%7},{%8,%9},{%0,%1,%2,%3};\n"
        : "+f"(c[0]), "+f"(c[1]), "+f"(c[2]), "+f"(c[3])
        : "r"(a[0]), "r"(a[1]), "r"(a[2]), "r"(a[3]), "r"(b[0]), "r"(b[1]));
}

// block tile 128x64, K-chunk 16. 8 warps: mw=(warp>>1)*32, nw=(warp&1)*32.
// warp tile 32x32 = 2 Mtiles x 4 Ntiles of m16n8k8.
__device__ __forceinline__ void mma_compute(const float (*As)[20], const float (*Bs)[72],
                                            float acc[2][4][4], int lane, int mw, int nw) {
    int g = lane >> 2, t = lane & 3;
#pragma unroll
    for (int ks = 0; ks < 2; ks++) {
        int k8 = ks * 8;
        unsigned a[2][4], b[4][2];
#pragma unroll
        for (int mt = 0; mt < 2; mt++) {
            int r = mw + mt * 16 + g;
            a[mt][0] = __float_as_uint(As[r][k8 + t]);
            a[mt][1] = __float_as_uint(As[r + 8][k8 + t]);
            a[mt][2] = __float_as_uint(As[r][k8 + t + 4]);
            a[mt][3] = __float_as_uint(As[r + 8][k8 + t + 4]);
        }
#pragma unroll
        for (int nt = 0; nt < 4; nt++) {
            int cn = nw + nt * 8 + g;
            b[nt][0] = __float_as_uint(Bs[k8 + t][cn]);
            b[nt][1] = __float_as_uint(Bs[k8 + t + 4][cn]);
        }
#pragma unroll
        for (int mt = 0; mt < 2; mt++)
#pragma unroll
            for (int nt = 0; nt < 4; nt++)
                mma8(acc[mt][nt], a[mt], b[nt]);
    }
}

// ---------------- LayerNorm ----------------------------------------------------
__global__ void ln_kernel(const float* __restrict__ x, const float* __restrict__ gw,
                          const float* __restrict__ gb, int which) {
    float* out = which ? g_h2 : g_h;
    int row = blockIdx.x, tid = threadIdx.x;
    const float* xp = x + row * DD;
    float v0 = xp[tid], v1 = xp[tid + 256], v2 = xp[tid + 512];
    float s = v0 + v1 + v2;
    float s2 = v0 * v0 + v1 * v1 + v2 * v2;
#pragma unroll
    for (int o = 16; o; o >>= 1) {
        s  += __shfl_xor_sync(0xffffffffu, s, o);
        s2 += __shfl_xor_sync(0xffffffffu, s2, o);
    }
    __shared__ float r1[8], r2[8];
    if ((tid & 31) == 0) { r1[tid >> 5] = s; r2[tid >> 5] = s2; }
    __syncthreads();
    s = 0.f; s2 = 0.f;
#pragma unroll
    for (int i = 0; i < 8; i++) { s += r1[i]; s2 += r2[i]; }
    float mu = s * (1.f / DD);
    float var = s2 * (1.f / DD) - mu * mu;
    float rs = rsqrtf(var + 1e-5f);
    float* op = out + row * DD;
    op[tid]       = (v0 - mu) * rs * gw[tid]       + gb[tid];
    op[tid + 256] = (v1 - mu) * rs * gw[tid + 256] + gb[tid + 256];
    op[tid + 512] = (v2 - mu) * rs * gw[tid + 512] + gb[tid + 512];
}

// ---------------- QKV projection (tf32 mma) ------------------------------------
// grid = (16, 36); y selects matrix+head. Output layout [B,H,T,HS].
__global__ __launch_bounds__(256) void qkv_gemm(
    const float* __restrict__ Wq, const float* __restrict__ Wk, const float* __restrict__ Wv) {
    __shared__ float As[2][128][20];
    __shared__ float Bs[2][16][72];
    int tid = threadIdx.x, lane = tid & 31, warp = tid >> 5;
    int mw = (warp >> 1) * 32, nw = (warp & 1) * 32;
    int m0 = blockIdx.x * 128;
    int y = blockIdx.y;
    const float* W; float* dst; int h;
    if (y < 12)      { W = Wq; dst = g_q; h = y; }
    else if (y < 24) { W = Wk; dst = g_k; h = y - 12; }
    else             { W = Wv; dst = g_v; h = y - 24; }
    const float* wb = W + (size_t)h * DD * HSZ;

    int ar = tid >> 2, ac = (tid & 3) * 4;       // A: rows via f=tid+i*256
    int ar1 = (tid + 256) >> 2, ac1 = ((tid + 256) & 3) * 4;
    int br = tid >> 4, bc = (tid & 15) * 4;      // B: 16 rows x 16 f4

    float4 ra0, ra1, rb;
    float acc[2][4][4] = {};

    ra0 = *(const float4*)(g_h + (size_t)(m0 + ar) * DD + ac);
    ra1 = *(const float4*)(g_h + (size_t)(m0 + ar1) * DD + ac1);
    rb  = *(const float4*)(wb + (size_t)br * HSZ + bc);
#pragma unroll 1
    for (int c = 0; c < 48; c++) {
        int buf = c & 1;
        {   // store prefetched chunk
            float4 t0 = make_float4(f2tff(ra0.x), f2tff(ra0.y), f2tff(ra0.z), f2tff(ra0.w));
            float4 t1 = make_float4(f2tff(ra1.x), f2tff(ra1.y), f2tff(ra1.z), f2tff(ra1.w));
            float4 t2 = make_float4(f2tff(rb.x), f2tff(rb.y), f2tff(rb.z), f2tff(rb.w));
            *(float4*)&As[buf][ar][ac]   = t0;
            *(float4*)&As[buf][ar1][ac1] = t1;
            *(float4*)&Bs[buf][br][bc]   = t2;
        }
        __syncthreads();
        if (c < 47) {
            int kk = (c + 1) * 16;
            ra0 = *(const float4*)(g_h + (size_t)(m0 + ar) * DD + kk + ac);
            ra1 = *(const float4*)(g_h + (size_t)(m0 + ar1) * DD + kk + ac1);
            rb  = *(const float4*)(wb + (size_t)(kk + br) * HSZ + bc);
        }
        mma_compute(As[buf], Bs[buf], acc, lane, mw, nw);
        __syncthreads();
    }

    int g = lane >> 2, t = lane & 3;
#pragma unroll
    for (int mt = 0; mt < 2; mt++) {
#pragma unroll
        for (int nt = 0; nt < 4; nt++) {
            int col = nw + nt * 8 + 2 * t;
#pragma unroll
            for (int half = 0; half < 2; half++) {
                int m = m0 + mw + mt * 16 + g + half * 8;
                int b_ = m >> 10, tt_ = m & 1023;
                float* o = dst + (((size_t)(b_ * HH + h) * TT + tt_) << 6);
                o[col]     = acc[mt][nt][half * 2];
                o[col + 1] = acc[mt][nt][half * 2 + 1];
            }
        }
    }
}

// ---------------- causal attention (flash-style, fp32) -------------------------
__global__ __launch_bounds__(128) void attn_kernel() {
    __shared__ float ksh[32][64];
    __shared__ float vsh[32][64];
    __shared__ float psh[128][33];
    int qt = blockIdx.x, h = blockIdx.y, b = blockIdx.z;
    int tid = threadIdx.x;
    int qi = qt * 128 + tid;
    const float scale = rsqrtf((float)DD);
    const float* qp = g_q + (((size_t)(b * HH) + h) * TT + qi) * HSZ;
    float qreg[64];
#pragma unroll
    for (int d = 0; d < 64; d++) qreg[d] = qp[d] * scale;
    float acc[64];
#pragma unroll
    for (int d = 0; d < 64; d++) acc[d] = 0.f;
    float m = -1e30f, l = 0.f;
    int ntiles = (qt + 1) * 4;
    const float* kbase = g_k + ((size_t)(b * HH) + h) * TT * HSZ;
    const float* vbase = g_v + ((size_t)(b * HH) + h) * TT * HSZ;
    for (int kt = 0; kt < ntiles; kt++) {
        const float* kp = kbase + kt * 32 * 64;
        const float* vp = vbase + kt * 32 * 64;
#pragma unroll
        for (int i = 0; i < 16; i++) {
            int idx = tid + i * 128;
            ksh[idx >> 6][idx & 63] = kp[idx];
            vsh[idx >> 6][idx & 63] = vp[idx];
        }
        __syncthreads();
        float mt = m;
        for (int j = 0; j < 32; j++) {
            int key = kt * 32 + j;
            float s = -1e30f;
            if (key <= qi) {
                s = 0.f;
#pragma unroll
                for (int d = 0; d < 64; d++) s += qreg[d] * ksh[j][d];
            }
            psh[tid][j] = s;
            mt = fmaxf(mt, s);
        }
        float r = __expf(m - mt);
        l *= r;
#pragma unroll
        for (int d = 0; d < 64; d++) acc[d] *= r;
        float lsum = 0.f;
        for (int j = 0; j < 32; j++) {
            float p = __expf(psh[tid][j] - mt);
            lsum += p;
            psh[tid][j] = p;
        }
        l += lsum;
        for (int j = 0; j < 32; j++) {
            float p = psh[tid][j];
#pragma unroll
            for (int d = 0; d < 64; d++) acc[d] += p * vsh[j][d];
        }
        m = mt;
        __syncthreads();
    }
    float inv = 1.f / l;
    float* op = g_att + ((size_t)(b * TT) + qi) * DD + h * HSZ;
#pragma unroll
    for (int d = 0; d < 64; d++) op[d] = acc[d] * inv;
}

// ---------------- output projection + residual (tf32 mma) ----------------------
// grid = (16, 12)
__global__ __launch_bounds__(256) void proj_gemm(
    const float* __restrict__ Wp, const float* __restrict__ bp,
    const float* __restrict__ x, float* __restrict__ out) {
    __shared__ float As[2][128][20];
    __shared__ float Bs[2][16][72];
    int tid = threadIdx.x, lane = tid & 31, warp = tid >> 5;
    int mw = (warp >> 1) * 32, nw = (warp & 1) * 32;
    int m0 = blockIdx.x * 128;
    int n0 = blockIdx.y * 64;

    int ar = tid >> 2, ac = (tid & 3) * 4;
    int ar1 = (tid + 256) >> 2, ac1 = ((tid + 256) & 3) * 4;
    int br = tid >> 4, bc = (tid & 15) * 4;

    float4 ra0, ra1, rb;
    float acc[2][4][4] = {};

    ra0 = *(const float4*)(g_att + (size_t)(m0 + ar) * DD + ac);
    ra1 = *(const float4*)(g_att + (size_t)(m0 + ar1) * DD + ac1);
    rb  = *(const float4*)(Wp + (size_t)br * DD + n0 + bc);
#pragma unroll 1
    for (int c = 0; c < 48; c++) {
        int buf = c & 1;
        {
            float4 t0 = make_float4(f2tff(ra0.x), f2tff(ra0.y), f2tff(ra0.z), f2tff(ra0.w));
            float4 t1 = make_float4(f2tff(ra1.x), f2tff(ra1.y), f2tff(ra1.z), f2tff(ra1.w));
            float4 t2 = make_float4(f2tff(rb.x), f2tff(rb.y), f2tff(rb.z), f2tff(rb.w));
            *(float4*)&As[buf][ar][ac]   = t0;
            *(float4*)&As[buf][ar1][ac1] = t1;
            *(float4*)&Bs[buf][br][bc]   = t2;
        }
        __syncthreads();
        if (c < 47) {
            int kk = (c + 1) * 16;
            ra0 = *(const float4*)(g_att + (size_t)(m0 + ar) * DD + kk + ac);
            ra1 = *(const float4*)(g_att + (size_t)(m0 + ar1) * DD + kk + ac1);
            rb  = *(const float4*)(Wp + (size_t)(kk + br) * DD + n0 + bc);
        }
        mma_compute(As[buf], Bs[buf], acc, lane, mw, nw);
        __syncthreads();
    }

    int g = lane >> 2, t = lane & 3;
#pragma unroll
    for (int mt = 0; mt < 2; mt++) {
#pragma unroll
        for (int nt = 0; nt < 4; nt++) {
            int col = n0 + nw + nt * 8 + 2 * t;
#pragma unroll
            for (int half = 0; half < 2; half++) {
                int m = m0 + mw + mt * 16 + g + half * 8;
                out[(size_t)m * DD + col]     = acc[mt][nt][half * 2]     + bp[col]     + x[(size_t)m * DD + col];
                out[(size_t)m * DD + col + 1] = acc[mt][nt][half * 2 + 1] + bp[col + 1] + x[(size_t)m * DD + col + 1];
            }
        }
    }
}

// ---------------- MoE gate (top-1 == argmax, weight == 1.0 exactly) ------------
__global__ void gate_kernel(const float* __restrict__ Wg) {
    int gtid = blockIdx.x * blockDim.x + threadIdx.x;
    int warp = gtid >> 5, lane = gtid & 31;
    if (warp >= NN) return;
    const float* hp = g_h2 + (size_t)warp * DD;
    float best = -1e30f; int bi = 0;
    for (int e = 0; e < EE; e++) {
        float s = 0.f;
        for (int i = lane; i < DD; i += 32) s += hp[i] * Wg[i * EE + e];
#pragma unroll
        for (int o = 16; o; o >>= 1) s += __shfl_xor_sync(0xffffffffu, s, o);
        if (s > best) { best = s; bi = e; }
    }
    if (lane == 0) g_sel[warp] = bi;
}

__global__ void moe_zero() { int t = threadIdx.x; if (t < EE) { g_cnt[t] = 0; g_cur[t] = 0; } }
__global__ void moe_count() {
    int n = blockIdx.x * 256 + threadIdx.x;
    if (n < NN) atomicAdd(&g_cnt[g_sel[n]], 1);
}
__global__ void moe_scan() {
    if (threadIdx.x == 0) {
        int o = 0;
        for (int e = 0; e < EE; e++) { g_off[e] = o; o += ((g_cnt[e] + 127) >> 7) << 7; }
        g_off[EE] = o;
    }
}
__global__ void moe_scatter() {
    int n = blockIdx.x * 256 + threadIdx.x;
    if (n < NN) {
        int e = g_sel[n];
        int p = atomicAdd(&g_cur[e], 1);
        g_perm[g_off[e] + p] = n;
    }
}

// ---------------- expert FFN1: hid = relu(h2[perm] @ W1[e] + b1[e]) ------------
// grid = (24, 48)
__global__ __launch_bounds__(256) void ffn1_gemm(const float* __restrict__ W1,
                                                 const float* __restrict__ b1) {
    int row0 = blockIdx.x * 128;
    if (row0 >= g_off[EE]) return;
    int e = 0;
#pragma unroll
    for (int i = 1; i < EE; i++) if (row0 >= g_off[i]) e = i;
    int valid = g_cnt[e] - (row0 - g_off[e]);
    if (valid > 128) valid = 128;
    __shared__ int toks[128];
    __shared__ float As[2][128][20];
    __shared__ float Bs[2][16][72];
    int tid = threadIdx.x, lane = tid & 31, warp = tid >> 5;
    int mw = (warp >> 1) * 32, nw = (warp & 1) * 32;
    if (tid < 128) toks[tid] = (tid < valid) ? g_perm[row0 + tid] : g_perm[row0];
    __syncthreads();
    int n0 = blockIdx.y * 64;
    const float* wb = W1 + (size_t)e * DD * DFF;

    int ar = tid >> 2, ac = (tid & 3) * 4;
    int ar1 = (tid + 256) >> 2, ac1 = ((tid + 256) & 3) * 4;
    int br = tid >> 4, bc = (tid & 15) * 4;
    int tok0 = toks[ar], tok1 = toks[ar1];

    float4 ra0, ra1, rb;
    float acc[2][4][4] = {};

    ra0 = *(const float4*)(g_h2 + (size_t)tok0 * DD + ac);
    ra1 = *(const float4*)(g_h2 + (size_t)tok1 * DD + ac1);
    rb  = *(const float4*)(wb + (size_t)br * DFF + n0 + bc);
#pragma unroll 1
    for (int c = 0; c < 48; c++) {
        int buf = c & 1;
        {
            float4 t0 = make_float4(f2tff(ra0.x), f2tff(ra0.y), f2tff(ra0.z), f2tff(ra0.w));
            float4 t1 = make_float4(f2tff(ra1.x), f2tff(ra1.y), f2tff(ra1.z), f2tff(ra1.w));
            float4 t2 = make_float4(f2tff(rb.x), f2tff(rb.y), f2tff(rb.z), f2tff(rb.w));
            *(float4*)&As[buf][ar][ac]   = t0;
            *(float4*)&As[buf][ar1][ac1] = t1;
            *(float4*)&Bs[buf][br][bc]   = t2;
        }
        __syncthreads();
        if (c < 47) {
            int kk = (c + 1) * 16;
            ra0 = *(const float4*)(g_h2 + (size_t)tok0 * DD + kk + ac);
            ra1 = *(const float4*)(g_h2 + (size_t)tok1 * DD + kk + ac1);
            rb  = *(const float4*)(wb + (size_t)(kk + br) * DFF + n0 + bc);
        }
        mma_compute(As[buf], Bs[buf], acc, lane, mw, nw);
        __syncthreads();
    }

    int g = lane >> 2, t = lane & 3;
#pragma unroll
    for (int mt = 0; mt < 2; mt++) {
#pragma unroll
        for (int nt = 0; nt < 4; nt++) {
            int col = n0 + nw + nt * 8 + 2 * t;
#pragma unroll
            for (int half = 0; half < 2; half++) {
                int lr = mw + mt * 16 + g + half * 8;
                if (lr < valid) {
                    float v0 = acc[mt][nt][half * 2]     + b1[(size_t)e * DFF + col];
                    float v1 = acc[mt][nt][half * 2 + 1] + b1[(size_t)e * DFF + col + 1];
                    g_hid[(size_t)(row0 + lr) * DFF + col]     = v0 > 0.f ? v0 : 0.f;
                    g_hid[(size_t)(row0 + lr) * DFF + col + 1] = v1 > 0.f ? v1 : 0.f;
                }
            }
        }
    }
}

// ---------------- expert FFN2: out[tok] += hid @ W2[e] + b2[e] -----------------
// grid = (24, 12), K = 3072 -> 192 chunks
__global__ __launch_bounds__(256) void ffn2_gemm(const float* __restrict__ W2,
                                                 const float* __restrict__ b2,
                                                 float* __restrict__ out) {
    int row0 = blockIdx.x * 128;
    if (row0 >= g_off[EE]) return;
    int e = 0;
#pragma unroll
    for (int i = 1; i < EE; i++) if (row0 >= g_off[i]) e = i;
    int valid = g_cnt[e] - (row0 - g_off[e]);
    if (valid > 128) valid = 128;
    __shared__ int toks[128];
    __shared__ float As[2][128][20];
    __shared__ float Bs[2][16][72];
    int tid = threadIdx.x, lane = tid & 31, warp = tid >> 5;
    int mw = (warp >> 1) * 32, nw = (warp & 1) * 32;
    if (tid < 128) toks[tid] = (tid < valid) ? g_perm[row0 + tid] : 0;
    __syncthreads();
    int n0 = blockIdx.y * 64;
    const float* wb = W2 + (size_t)e * DFF * DD;

    int ar = tid >> 2, ac = (tid & 3) * 4;
    int ar1 = (tid + 256) >> 2, ac1 = ((tid + 256) & 3) * 4;
    int br = tid >> 4, bc = (tid & 15) * 4;

    float4 ra0, ra1, rb;
    float acc[2][4][4] = {};

    ra0 = *(const float4*)(g_hid + (size_t)(row0 + ar) * DFF + ac);
    ra1 = *(const float4*)(g_hid + (size_t)(row0 + ar1) * DFF + ac1);
    rb  = *(const float4*)(wb + (size_t)br * DD + n0 + bc);
#pragma unroll 1
    for (int c = 0; c < 192; c++) {
        int buf = c & 1;
        {
            float4 t0 = make_float4(f2tff(ra0.x), f2tff(ra0.y), f2tff(ra0.z), f2tff(ra0.w));
            float4 t1 = make_float4(f2tff(ra1.x), f2tff(ra1.y), f2tff(ra1.z), f2tff(ra1.w));
            float4 t2 = make_float4(f2tff(rb.x), f2tff(rb.y), f2tff(rb.z), f2tff(rb.w));
            *(float4*)&As[buf][ar][ac]   = t0;
            *(float4*)&As[buf][ar1][ac1] = t1;
            *(float4*)&Bs[buf][br][bc]   = t2;
        }
        __syncthreads();
        if (c < 191) {
            int kk = (c + 1) * 16;
            ra0 = *(const float4*)(g_hid + (size_t)(row0 + ar) * DFF + kk + ac);
            ra1 = *(const float4*)(g_hid + (size_t)(row0 + ar1) * DFF + kk + ac1);
            rb  = *(const float4*)(wb + (size_t)(kk + br) * DD + n0 + bc);
        }
        mma_compute(As[buf], Bs[buf], acc, lane, mw, nw);
        __syncthreads();
    }

    int g = lane >> 2, t = lane & 3;
#pragma unroll
    for (int mt = 0; mt < 2; mt++) {
#pragma unroll
        for (int nt = 0; nt < 4; nt++) {
            int col = n0 + nw + nt * 8 + 2 * t;
#pragma unroll
            for (int half = 0; half < 2; half++) {
                int lr = mw + mt * 16 + g + half * 8;
                if (lr < valid) {
                    int tok = toks[lr];
                    out[(size_t)tok * DD + col]     += acc[mt][nt][half * 2]     + b2[(size_t)e * DD + col];
                    out[(size_t)tok * DD + col + 1] += acc[mt][nt][half * 2 + 1] + b2[(size_t)e * DD + col + 1];
                }
            }
        }
    }
}

// ---------------- launch -------------------------------------------------------
extern "C" void kernel_launch(void* const* d_in, const int* in_sizes, int n_in,
                              void* d_out, int out_size) {
    const float* x     = (const float*)d_in[0];
    const float* ln1_g = (const float*)d_in[1];
    const float* ln1_b = (const float*)d_in[2];
    const float* ln2_g = (const float*)d_in[3];
    const float* ln2_b = (const float*)d_in[4];
    const float* Wq    = (const float*)d_in[5];
    const float* Wk    = (const float*)d_in[6];
    const float* Wv    = (const float*)d_in[7];
    const float* Wp    = (const float*)d_in[8];
    const float* bp    = (const float*)d_in[9];
    const float* Wg    = (const float*)d_in[10];
    const float* W1    = (const float*)d_in[11];
    const float* b1    = (const float*)d_in[12];
    const float* W2    = (const float*)d_in[13];
    const float* b2    = (const float*)d_in[14];
    float* out = (float*)d_out;

    ln_kernel<<<NN, 256>>>(x, ln1_g, ln1_b, 0);
    qkv_gemm<<<dim3(NN / 128, 36), 256>>>(Wq, Wk, Wv);
    attn_kernel<<<dim3(TT / 128, HH, BB), 128>>>();
    proj_gemm<<<dim3(NN / 128, DD / 64), 256>>>(Wp, bp, x, out);
    ln_kernel<<<NN, 256>>>(out, ln2_g, ln2_b, 1);
    moe_zero<<<1, 32>>>();
    gate_kernel<<<NN * 32 / 256, 256>>>(Wg);
    moe_count<<<NN / 256, 256>>>();
    moe_scan<<<1, 1>>>();
    moe_scatter<<<NN / 256, 256>>>();
    ffn1_gemm<<<dim3(NPAD / 128, DFF / 64), 256>>>(W1, b1);
    ffn2_gemm<<<dim3(NPAD / 128, DD / 64), 256>>>(W2, b2, out);
}

// round 10
// speedup vs baseline: 2.1107x; 1.1366x over previous
#include <cuda_runtime.h>
#include <cstdint>

// Problem dims
#define BB 2
#define TT 1024
#define DD 768
#define HH 12
#define HSZ 64
#define EE 8
#define DFF 3072
#define NN 2048
#define NPAD 3072

// GEMM tiling
#define AS_STRIDE 36           // bank: 4g+t distinct
#define BS_STRIDE 136          // bank: 8t+g distinct
#define AS_BUF (128 * AS_STRIDE)      // 4608 floats
#define BS_BUF (32 * BS_STRIDE)       // 4352 floats
#define B_BASE (2 * AS_BUF)           // 9216
#define SMEM_FLOATS (2 * AS_BUF + 2 * BS_BUF)   // 17920 floats = 71680 B

// ---------------- scratch ------------------------------------------------------
__device__ float g_h[NN * DD];
__device__ float g_q[NN * DD];
__device__ float g_k[NN * DD];
__device__ float g_v[NN * DD];
__device__ float g_att[NN * DD];
__device__ float g_h2[NN * DD];
__device__ float g_hid[NPAD * DFF];
__device__ int   g_sel[NN];
__device__ int   g_cnt[EE];
__device__ int   g_cur[EE];
__device__ int   g_off[EE + 1];
__device__ int   g_perm[NPAD];

// ---------------- cp.async + mma helpers --------------------------------------
__device__ __forceinline__ void cpa16(unsigned s, const float* g) {
    asm volatile("cp.async.ca.shared.global [%0], [%1], 16;\n" :: "r"(s), "l"(g));
}
__device__ __forceinline__ void cp_commit() { asm volatile("cp.async.commit_group;\n"); }
__device__ __forceinline__ void cp_wait1() { asm volatile("cp.async.wait_group 1;\n"); }
__device__ __forceinline__ void cp_wait0() { asm volatile("cp.async.wait_group 0;\n"); }

// round-to-nearest tf32 conversion (unbiased; truncation biases compound!)
__device__ __forceinline__ unsigned cvt_tf32(float v) {
    unsigned r;
    asm("cvt.rna.tf32.f32 %0, %1;" : "=r"(r) : "f"(v));
    return r;
}

__device__ __forceinline__ void mma8(float* c, const unsigned* a, const unsigned* b) {
    asm volatile(
        "mma.sync.aligned.m16n8k8.row.col.f32.tf32.tf32.f32 "
        "{%0,%1,%2,%3},{%4,%5,%6,%7},{%8,%9},{%0,%1,%2,%3};\n"
        : "+f"(c[0]), "+f"(c[1]), "+f"(c[2]), "+f"(c[3])
        : "r"(a[0]), "r"(a[1]), "r"(a[2]), "r"(a[3]), "r"(b[0]), "r"(b[1]));
}

// compute one 32-wide K chunk: warp tile 64x32 (4 mt x 4 nt), rna-rounded tf32
__device__ __forceinline__ void mma_chunk(const float* __restrict__ sA,
                                          const float* __restrict__ sB,
                                          float acc[4][4][4], int g, int t, int mw, int nw) {
#pragma unroll
    for (int ks = 0; ks < 4; ks++) {
        int k8 = ks * 8;
        unsigned a[4][4], b[4][2];
#pragma unroll
        for (int mt = 0; mt < 4; mt++) {
            int r = mw + mt * 16 + g;
            a[mt][0] = cvt_tf32(sA[r * AS_STRIDE + k8 + t]);
            a[mt][1] = cvt_tf32(sA[(r + 8) * AS_STRIDE + k8 + t]);
            a[mt][2] = cvt_tf32(sA[r * AS_STRIDE + k8 + t + 4]);
            a[mt][3] = cvt_tf32(sA[(r + 8) * AS_STRIDE + k8 + t + 4]);
        }
#pragma unroll
        for (int nt = 0; nt < 4; nt++) {
            int cn = nw + nt * 8 + g;
            b[nt][0] = cvt_tf32(sB[(k8 + t) * BS_STRIDE + cn]);
            b[nt][1] = cvt_tf32(sB[(k8 + t + 4) * BS_STRIDE + cn]);
        }
#pragma unroll
        for (int mt = 0; mt < 4; mt++)
#pragma unroll
            for (int nt = 0; nt < 4; nt++)
                mma8(acc[mt][nt], a[mt], b[nt]);
    }
}

// ---------------- LayerNorm ----------------------------------------------------
__global__ void ln_kernel(const float* __restrict__ x, const float* __restrict__ gw,
                          const float* __restrict__ gb, int which) {
    float* out = which ? g_h2 : g_h;
    int row = blockIdx.x, tid = threadIdx.x;
    const float* xp = x + (size_t)row * DD;
    float v0 = xp[tid], v1 = xp[tid + 256], v2 = xp[tid + 512];
    float s = v0 + v1 + v2;
    float s2 = v0 * v0 + v1 * v1 + v2 * v2;
#pragma unroll
    for (int o = 16; o; o >>= 1) {
        s  += __shfl_xor_sync(0xffffffffu, s, o);
        s2 += __shfl_xor_sync(0xffffffffu, s2, o);
    }
    __shared__ float r1[8], r2[8];
    if ((tid & 31) == 0) { r1[tid >> 5] = s; r2[tid >> 5] = s2; }
    __syncthreads();
    s = 0.f; s2 = 0.f;
#pragma unroll
    for (int i = 0; i < 8; i++) { s += r1[i]; s2 += r2[i]; }
    float mu = s * (1.f / DD);
    float var = s2 * (1.f / DD) - mu * mu;
    float rs = rsqrtf(var + 1e-5f);
    float* op = out + (size_t)row * DD;
    op[tid]       = (v0 - mu) * rs * gw[tid]       + gb[tid];
    op[tid + 256] = (v1 - mu) * rs * gw[tid + 256] + gb[tid + 256];
    op[tid + 512] = (v2 - mu) * rs * gw[tid + 512] + gb[tid + 512];
}

// ---------------- QKV gemm: [2048,768] x [768,768] per matrix ------------------
// grid (16, 18): y/6 -> matrix, y%6 -> ntile
__global__ __launch_bounds__(256, 2) void qkv_tc(
    const float* __restrict__ Wq, const float* __restrict__ Wk, const float* __restrict__ Wv) {
    extern __shared__ float sm[];
    int tid = threadIdx.x, lane = tid & 31, warp = tid >> 5;
    int g = lane >> 2, t = lane & 3;
    int mw = (warp >> 2) * 64, nw = (warp & 3) * 32;
    int m0 = blockIdx.x * 128;
    int y = blockIdx.y;
    const float* W = (y < 6) ? Wq : (y < 12 ? Wk : Wv);
    float* dst = (y < 6) ? g_q : (y < 12 ? g_k : g_v);
    int n0 = (y % 6) * 128;

    unsigned sbase = (unsigned)__cvta_generic_to_shared(sm);
    const float* arow[4]; unsigned asmo[4];
    const float* brow[4]; unsigned bsmo[4];
#pragma unroll
    for (int i = 0; i < 4; i++) {
        int f = tid + i * 256;
        int r = f >> 3, kq = (f & 7) * 4;
        arow[i] = g_h + (size_t)(m0 + r) * DD + kq;
        asmo[i] = sbase + (r * AS_STRIDE + kq) * 4;
        int kk = f >> 5, nq = (f & 31) * 4;
        int j = n0 + nq;
        brow[i] = W + (size_t)(j >> 6) * DD * HSZ + (j & 63) + kk * HSZ;
        bsmo[i] = sbase + (B_BASE + kk * BS_STRIDE + nq) * 4;
    }
    float acc[4][4][4] = {};
    const int NC = DD / 32;  // 24
#pragma unroll
    for (int p = 0; p < 2; p++) {
        int k0 = p * 32;
#pragma unroll
        for (int i = 0; i < 4; i++) cpa16(asmo[i] + p * AS_BUF * 4, arow[i] + k0);
#pragma unroll
        for (int i = 0; i < 4; i++) cpa16(bsmo[i] + p * BS_BUF * 4, brow[i] + k0 * HSZ);
        cp_commit();
    }
#pragma unroll 1
    for (int c = 0; c < NC; c++) {
        if (c + 1 < NC) cp_wait1(); else cp_wait0();
        __syncthreads();
        int buf = c & 1;
        mma_chunk(sm + buf * AS_BUF, sm + B_BASE + buf * BS_BUF, acc, g, t, mw, nw);
        __syncthreads();
        if (c + 2 < NC) {
            int k0 = (c + 2) * 32;
#pragma unroll
            for (int i = 0; i < 4; i++) cpa16(asmo[i] + buf * AS_BUF * 4, arow[i] + k0);
#pragma unroll
            for (int i = 0; i < 4; i++) cpa16(bsmo[i] + buf * BS_BUF * 4, brow[i] + k0 * HSZ);
            cp_commit();
        }
    }
#pragma unroll
    for (int mt = 0; mt < 4; mt++) {
#pragma unroll
        for (int nt = 0; nt < 4; nt++) {
            int col = nw + nt * 8 + 2 * t;
            int j = n0 + col, h = j >> 6, s_ = j & 63;
#pragma unroll
            for (int half = 0; half < 2; half++) {
                int m = m0 + mw + mt * 16 + g + half * 8;
                int b_ = m >> 10, t_ = m & 1023;
                float2 v = make_float2(acc[mt][nt][half * 2], acc[mt][nt][half * 2 + 1]);
                *(float2*)(dst + (((size_t)(b_ * HH + h) * TT + t_) << 6) + s_) = v;
            }
        }
    }
}

// ---------------- causal attention (flash-style, fp32) -------------------------
__global__ __launch_bounds__(128) void attn_kernel() {
    __shared__ float ksh[32][64];
    __shared__ float vsh[32][64];
    __shared__ float psh[128][33];
    int qt = blockIdx.x, h = blockIdx.y, b = blockIdx.z;
    int tid = threadIdx.x;
    int qi = qt * 128 + tid;
    const float scale = rsqrtf((float)DD);
    const float* qp = g_q + (((size_t)(b * HH) + h) * TT + qi) * HSZ;
    float qreg[64];
#pragma unroll
    for (int d = 0; d < 64; d++) qreg[d] = qp[d] * scale;
    float acc[64];
#pragma unroll
    for (int d = 0; d < 64; d++) acc[d] = 0.f;
    float m = -1e30f, l = 0.f;
    int ntiles = (qt + 1) * 4;
    const float* kbase = g_k + ((size_t)(b * HH) + h) * TT * HSZ;
    const float* vbase = g_v + ((size_t)(b * HH) + h) * TT * HSZ;
    for (int kt = 0; kt < ntiles; kt++) {
        const float* kp = kbase + kt * 32 * 64;
        const float* vp = vbase + kt * 32 * 64;
#pragma unroll
        for (int i = 0; i < 16; i++) {
            int idx = tid + i * 128;
            ksh[idx >> 6][idx & 63] = kp[idx];
            vsh[idx >> 6][idx & 63] = vp[idx];
        }
        __syncthreads();
        float mt = m;
        for (int j = 0; j < 32; j++) {
            int key = kt * 32 + j;
            float s = -1e30f;
            if (key <= qi) {
                s = 0.f;
#pragma unroll
                for (int d = 0; d < 64; d++) s += qreg[d] * ksh[j][d];
            }
            psh[tid][j] = s;
            mt = fmaxf(mt, s);
        }
        float r = __expf(m - mt);
        l *= r;
#pragma unroll
        for (int d = 0; d < 64; d++) acc[d] *= r;
        float lsum = 0.f;
        for (int j = 0; j < 32; j++) {
            float p = __expf(psh[tid][j] - mt);
            lsum += p;
            psh[tid][j] = p;
        }
        l += lsum;
        for (int j = 0; j < 32; j++) {
            float p = psh[tid][j];
#pragma unroll
            for (int d = 0; d < 64; d++) acc[d] += p * vsh[j][d];
        }
        m = mt;
        __syncthreads();
    }
    float inv = 1.f / l;
    float* op = g_att + ((size_t)(b * TT) + qi) * DD + h * HSZ;
#pragma unroll
    for (int d = 0; d < 64; d++) op[d] = acc[d] * inv;
}

// ---------------- output projection + residual ---------------------------------
// grid (16, 6)
__global__ __launch_bounds__(256, 2) void proj_tc(
    const float* __restrict__ Wp, const float* __restrict__ bp,
    const float* __restrict__ x, float* __restrict__ out) {
    extern __shared__ float sm[];
    int tid = threadIdx.x, lane = tid & 31, warp = tid >> 5;
    int g = lane >> 2, t = lane & 3;
    int mw = (warp >> 2) * 64, nw = (warp & 3) * 32;
    int m0 = blockIdx.x * 128;
    int n0 = blockIdx.y * 128;

    unsigned sbase = (unsigned)__cvta_generic_to_shared(sm);
    const float* arow[4]; unsigned asmo[4];
    const float* brow[4]; unsigned bsmo[4];
#pragma unroll
    for (int i = 0; i < 4; i++) {
        int f = tid + i * 256;
        int r = f >> 3, kq = (f & 7) * 4;
        arow[i] = g_att + (size_t)(m0 + r) * DD + kq;
        asmo[i] = sbase + (r * AS_STRIDE + kq) * 4;
        int kk = f >> 5, nq = (f & 31) * 4;
        brow[i] = Wp + (size_t)kk * DD + n0 + nq;
        bsmo[i] = sbase + (B_BASE + kk * BS_STRIDE + nq) * 4;
    }
    float acc[4][4][4] = {};
    const int NC = DD / 32;
#pragma unroll
    for (int p = 0; p < 2; p++) {
        int k0 = p * 32;
#pragma unroll
        for (int i = 0; i < 4; i++) cpa16(asmo[i] + p * AS_BUF * 4, arow[i] + k0);
#pragma unroll
        for (int i = 0; i < 4; i++) cpa16(bsmo[i] + p * BS_BUF * 4, brow[i] + (size_t)k0 * DD);
        cp_commit();
    }
#pragma unroll 1
    for (int c = 0; c < NC; c++) {
        if (c + 1 < NC) cp_wait1(); else cp_wait0();
        __syncthreads();
        int buf = c & 1;
        mma_chunk(sm + buf * AS_BUF, sm + B_BASE + buf * BS_BUF, acc, g, t, mw, nw);
        __syncthreads();
        if (c + 2 < NC) {
            int k0 = (c + 2) * 32;
#pragma unroll
            for (int i = 0; i < 4; i++) cpa16(asmo[i] + buf * AS_BUF * 4, arow[i] + k0);
#pragma unroll
            for (int i = 0; i < 4; i++) cpa16(bsmo[i] + buf * BS_BUF * 4, brow[i] + (size_t)k0 * DD);
            cp_commit();
        }
    }
#pragma unroll
    for (int mt = 0; mt < 4; mt++) {
#pragma unroll
        for (int nt = 0; nt < 4; nt++) {
            int col = n0 + nw + nt * 8 + 2 * t;
#pragma unroll
            for (int half = 0; half < 2; half++) {
                int m = m0 + mw + mt * 16 + g + half * 8;
                size_t idx = (size_t)m * DD + col;
                out[idx]     = acc[mt][nt][half * 2]     + bp[col]     + x[idx];
                out[idx + 1] = acc[mt][nt][half * 2 + 1] + bp[col + 1] + x[idx + 1];
            }
        }
    }
}

// ---------------- MoE gate + routing -------------------------------------------
__global__ void gate_kernel(const float* __restrict__ Wg) {
    int gtid = blockIdx.x * blockDim.x + threadIdx.x;
    int warp = gtid >> 5, lane = gtid & 31;
    if (warp >= NN) return;
    const float* hp = g_h2 + (size_t)warp * DD;
    float best = -1e30f; int bi = 0;
    for (int e = 0; e < EE; e++) {
        float s = 0.f;
        for (int i = lane; i < DD; i += 32) s += hp[i] * Wg[i * EE + e];
#pragma unroll
        for (int o = 16; o; o >>= 1) s += __shfl_xor_sync(0xffffffffu, s, o);
        if (s > best) { best = s; bi = e; }
    }
    if (lane == 0) g_sel[warp] = bi;
}

__global__ void moe_zero() { int t = threadIdx.x; if (t < EE) { g_cnt[t] = 0; g_cur[t] = 0; } }
__global__ void moe_count() {
    int n = blockIdx.x * 256 + threadIdx.x;
    if (n < NN) atomicAdd(&g_cnt[g_sel[n]], 1);
}
__global__ void moe_scan() {
    if (threadIdx.x == 0) {
        int o = 0;
        for (int e = 0; e < EE; e++) { g_off[e] = o; o += ((g_cnt[e] + 127) >> 7) << 7; }
        g_off[EE] = o;
    }
}
__global__ void moe_scatter() {
    int n = blockIdx.x * 256 + threadIdx.x;
    if (n < NN) {
        int e = g_sel[n];
        int p = atomicAdd(&g_cur[e], 1);
        g_perm[g_off[e] + p] = n;
    }
}

// ---------------- expert FFN1: hid = relu(h2[perm] @ W1[e] + b1[e]) ------------
// grid (24, 24)
__global__ __launch_bounds__(256, 2) void ffn1_tc(const float* __restrict__ W1,
                                                  const float* __restrict__ b1) {
    int row0 = blockIdx.x * 128;
    if (row0 >= g_off[EE]) return;
    int e = 0;
#pragma unroll
    for (int i = 1; i < EE; i++) if (row0 >= g_off[i]) e = i;
    int valid = g_cnt[e] - (row0 - g_off[e]);
    if (valid > 128) valid = 128;
    extern __shared__ float sm[];
    __shared__ int toks[128];
    int tid = threadIdx.x, lane = tid & 31, warp = tid >> 5;
    int g = lane >> 2, t = lane & 3;
    int mw = (warp >> 2) * 64, nw = (warp & 3) * 32;
    if (tid < 128) toks[tid] = (tid < valid) ? g_perm[row0 + tid] : g_perm[row0];
    __syncthreads();
    int n0 = blockIdx.y * 128;
    const float* wb = W1 + (size_t)e * DD * DFF;

    unsigned sbase = (unsigned)__cvta_generic_to_shared(sm);
    const float* arow[4]; unsigned asmo[4];
    const float* brow[4]; unsigned bsmo[4];
#pragma unroll
    for (int i = 0; i < 4; i++) {
        int f = tid + i * 256;
        int r = f >> 3, kq = (f & 7) * 4;
        arow[i] = g_h2 + (size_t)toks[r] * DD + kq;
        asmo[i] = sbase + (r * AS_STRIDE + kq) * 4;
        int kk = f >> 5, nq = (f & 31) * 4;
        brow[i] = wb + (size_t)kk * DFF + n0 + nq;
        bsmo[i] = sbase + (B_BASE + kk * BS_STRIDE + nq) * 4;
    }
    float acc[4][4][4] = {};
    const int NC = DD / 32;
#pragma unroll
    for (int p = 0; p < 2; p++) {
        int k0 = p * 32;
#pragma unroll
        for (int i = 0; i < 4; i++) cpa16(asmo[i] + p * AS_BUF * 4, arow[i] + k0);
#pragma unroll
        for (int i = 0; i < 4; i++) cpa16(bsmo[i] + p * BS_BUF * 4, brow[i] + (size_t)k0 * DFF);
        cp_commit();
    }
#pragma unroll 1
    for (int c = 0; c < NC; c++) {
        if (c + 1 < NC) cp_wait1(); else cp_wait0();
        __syncthreads();
        int buf = c & 1;
        mma_chunk(sm + buf * AS_BUF, sm + B_BASE + buf * BS_BUF, acc, g, t, mw, nw);
        __syncthreads();
        if (c + 2 < NC) {
            int k0 = (c + 2) * 32;
#pragma unroll
            for (int i = 0; i < 4; i++) cpa16(asmo[i] + buf * AS_BUF * 4, arow[i] + k0);
#pragma unroll
            for (int i = 0; i < 4; i++) cpa16(bsmo[i] + buf * BS_BUF * 4, brow[i] + (size_t)k0 * DFF);
            cp_commit();
        }
    }
#pragma unroll
    for (int mt = 0; mt < 4; mt++) {
#pragma unroll
        for (int nt = 0; nt < 4; nt++) {
            int col = n0 + nw + nt * 8 + 2 * t;
#pragma unroll
            for (int half = 0; half < 2; half++) {
                int lr = mw + mt * 16 + g + half * 8;
                if (lr < valid) {
                    float v0 = acc[mt][nt][half * 2]     + b1[(size_t)e * DFF + col];
                    float v1 = acc[mt][nt][half * 2 + 1] + b1[(size_t)e * DFF + col + 1];
                    float2 v = make_float2(v0 > 0.f ? v0 : 0.f, v1 > 0.f ? v1 : 0.f);
                    *(float2*)(g_hid + (size_t)(row0 + lr) * DFF + col) = v;
                }
            }
        }
    }
}

// ---------------- expert FFN2: out[tok] += hid @ W2[e] + b2[e] -----------------
// grid (24, 6), K = 3072
__global__ __launch_bounds__(256, 2) void ffn2_tc(const float* __restrict__ W2,
                                                  const float* __restrict__ b2,
                                                  float* __restrict__ out) {
    int row0 = blockIdx.x * 128;
    if (row0 >= g_off[EE]) return;
    int e = 0;
#pragma unroll
    for (int i = 1; i < EE; i++) if (row0 >= g_off[i]) e = i;
    int valid = g_cnt[e] - (row0 - g_off[e]);
    if (valid > 128) valid = 128;
    extern __shared__ float sm[];
    __shared__ int toks[128];
    int tid = threadIdx.x, lane = tid & 31, warp = tid >> 5;
    int g = lane >> 2, t = lane & 3;
    int mw = (warp >> 2) * 64, nw = (warp & 3) * 32;
    if (tid < 128) toks[tid] = (tid < valid) ? g_perm[row0 + tid] : 0;
    __syncthreads();
    int n0 = blockIdx.y * 128;
    const float* wb = W2 + (size_t)e * DFF * DD;

    unsigned sbase = (unsigned)__cvta_generic_to_shared(sm);
    const float* arow[4]; unsigned asmo[4];
    const float* brow[4]; unsigned bsmo[4];
#pragma unroll
    for (int i = 0; i < 4; i++) {
        int f = tid + i * 256;
        int r = f >> 3, kq = (f & 7) * 4;
        arow[i] = g_hid + (size_t)(row0 + r) * DFF + kq;
        asmo[i] = sbase + (r * AS_STRIDE + kq) * 4;
        int kk = f >> 5, nq = (f & 31) * 4;
        brow[i] = wb + (size_t)kk * DD + n0 + nq;
        bsmo[i] = sbase + (B_BASE + kk * BS_STRIDE + nq) * 4;
    }
    float acc[4][4][4] = {};
    const int NC = DFF / 32;   // 96
#pragma unroll
    for (int p = 0; p < 2; p++) {
        int k0 = p * 32;
#pragma unroll
        for (int i = 0; i < 4; i++) cpa16(asmo[i] + p * AS_BUF * 4, arow[i] + k0);
#pragma unroll
        for (int i = 0; i < 4; i++) cpa16(bsmo[i] + p * BS_BUF * 4, brow[i] + (size_t)k0 * DD);
        cp_commit();
    }
#pragma unroll 1
    for (int c = 0; c < NC; c++) {
        if (c + 1 < NC) cp_wait1(); else cp_wait0();
        __syncthreads();
        int buf = c & 1;
        mma_chunk(sm + buf * AS_BUF, sm + B_BASE + buf * BS_BUF, acc, g, t, mw, nw);
        __syncthreads();
        if (c + 2 < NC) {
            int k0 = (c + 2) * 32;
#pragma unroll
            for (int i = 0; i < 4; i++) cpa16(asmo[i] + buf * AS_BUF * 4, arow[i] + k0);
#pragma unroll
            for (int i = 0; i < 4; i++) cpa16(bsmo[i] + buf * BS_BUF * 4, brow[i] + (size_t)k0 * DD);
            cp_commit();
        }
    }
#pragma unroll
    for (int mt = 0; mt < 4; mt++) {
#pragma unroll
        for (int nt = 0; nt < 4; nt++) {
            int col = n0 + nw + nt * 8 + 2 * t;
#pragma unroll
            for (int half = 0; half < 2; half++) {
                int lr = mw + mt * 16 + g + half * 8;
                if (lr < valid) {
                    int tok = toks[lr];
                    size_t idx = (size_t)tok * DD + col;
                    out[idx]     += acc[mt][nt][half * 2]     + b2[(size_t)e * DD + col];
                    out[idx + 1] += acc[mt][nt][half * 2 + 1] + b2[(size_t)e * DD + col + 1];
                }
            }
        }
    }
}

// ---------------- launch -------------------------------------------------------
extern "C" void kernel_launch(void* const* d_in, const int* in_sizes, int n_in,
                              void* d_out, int out_size) {
    const float* x     = (const float*)d_in[0];
    const float* ln1_g = (const float*)d_in[1];
    const float* ln1_b = (const float*)d_in[2];
    const float* ln2_g = (const float*)d_in[3];
    const float* ln2_b = (const float*)d_in[4];
    const float* Wq    = (const float*)d_in[5];
    const float* Wk    = (const float*)d_in[6];
    const float* Wv    = (const float*)d_in[7];
    const float* Wp    = (const float*)d_in[8];
    const float* bp    = (const float*)d_in[9];
    const float* Wg    = (const float*)d_in[10];
    const float* W1    = (const float*)d_in[11];
    const float* b1    = (const float*)d_in[12];
    const float* W2    = (const float*)d_in[13];
    const float* b2    = (const float*)d_in[14];
    float* out = (float*)d_out;

    const int smem_bytes = SMEM_FLOATS * 4;   // 71680
    static bool attr_set = false;
    if (!attr_set) {
        cudaFuncSetAttribute(qkv_tc,  cudaFuncAttributeMaxDynamicSharedMemorySize, smem_bytes);
        cudaFuncSetAttribute(proj_tc, cudaFuncAttributeMaxDynamicSharedMemorySize, smem_bytes);
        cudaFuncSetAttribute(ffn1_tc, cudaFuncAttributeMaxDynamicSharedMemorySize, smem_bytes);
        cudaFuncSetAttribute(ffn2_tc, cudaFuncAttributeMaxDynamicSharedMemorySize, smem_bytes);
        attr_set = true;
    }

    ln_kernel<<<NN, 256>>>(x, ln1_g, ln1_b, 0);
    qkv_tc<<<dim3(NN / 128, 18), 256, smem_bytes>>>(Wq, Wk, Wv);
    attn_kernel<<<dim3(TT / 128, HH, BB), 128>>>();
    proj_tc<<<dim3(NN / 128, DD / 128), 256, smem_bytes>>>(Wp, bp, x, out);
    ln_kernel<<<NN, 256>>>(out, ln2_g, ln2_b, 1);
    moe_zero<<<1, 32>>>();
    gate_kernel<<<NN * 32 / 256, 256>>>(Wg);
    moe_count<<<NN / 256, 256>>>();
    moe_scan<<<1, 1>>>();
    moe_scatter<<<NN / 256, 256>>>();
    ffn1_tc<<<dim3(NPAD / 128, DFF / 128), 256, smem_bytes>>>(W1, b1);
    ffn2_tc<<<dim3(NPAD / 128, DD / 128), 256, smem_bytes>>>(W2, b2, out);
}

// round 12
// speedup vs baseline: 3.7259x; 1.7652x over previous
#include <cuda_runtime.h>
#include <cstdint>

// Problem dims
#define BB 2
#define TT 1024
#define DD 768
#define HH 12
#define HSZ 64
#define EE 8
#define DFF 3072
#define NN 2048
#define NPAD 3072

// GEMM tiling (3-stage pipeline)
#define AS_STRIDE 36                  // bank: 4g+t distinct
#define BS_STRIDE 136                 // bank: 8t+g distinct
#define AS_BUF (128 * AS_STRIDE)      // 4608 floats
#define BS_BUF (32 * BS_STRIDE)       // 4352 floats
#define B_BASE3 (3 * AS_BUF)          // 13824
#define SMEM_G_FLOATS (3 * (AS_BUF + BS_BUF))   // 26880 floats = 107520 B

// Attention smem layout (floats)
#define QS_STR 68
#define KS_STR 68
#define VS_STR 72
#define PS_STR 68
#define AQ 0
#define AK (128 * QS_STR)                       // 8704
#define AV (AK + 2 * 64 * KS_STR)               // 8704 + 8704 = 17408
#define AP (AV + 2 * 64 * VS_STR)               // 17408 + 9216 = 26624
#define ATT_SMEM_FLOATS (AP + 128 * PS_STR)     // 35328 floats = 141312 B

// ---------------- scratch ------------------------------------------------------
__device__ float g_h[NN * DD];
__device__ float g_q[NN * DD];
__device__ float g_k[NN * DD];
__device__ float g_v[NN * DD];
__device__ float g_att[NN * DD];
__device__ float g_h2[NN * DD];
__device__ float g_hid[NPAD * DFF];
__device__ int   g_sel[NN];
__device__ int   g_cnt[EE];
__device__ int   g_cur[EE];
__device__ int   g_off[EE + 1];
__device__ int   g_perm[NPAD];

// ---------------- helpers ------------------------------------------------------
__device__ __forceinline__ void cpa16(unsigned s, const float* g) {
    asm volatile("cp.async.ca.shared.global [%0], [%1], 16;\n" :: "r"(s), "l"(g));
}
__device__ __forceinline__ void cp_commit() { asm volatile("cp.async.commit_group;\n"); }
__device__ __forceinline__ void cp_wait1() { asm volatile("cp.async.wait_group 1;\n"); }
__device__ __forceinline__ void cp_wait0() { asm volatile("cp.async.wait_group 0;\n"); }

__device__ __forceinline__ unsigned cvt_tf32(float v) {
    unsigned r;
    asm("cvt.rna.tf32.f32 %0, %1;" : "=r"(r) : "f"(v));
    return r;
}
__device__ __forceinline__ float tf32f(float v) { return __uint_as_float(cvt_tf32(v)); }

__device__ __forceinline__ void mma8(float* c, const unsigned* a, const unsigned* b) {
    asm volatile(
        "mma.sync.aligned.m16n8k8.row.col.f32.tf32.tf32.f32 "
        "{%0,%1,%2,%3},{%4,%5,%6,%7},{%8,%9},{%0,%1,%2,%3};\n"
        : "+f"(c[0]), "+f"(c[1]), "+f"(c[2]), "+f"(c[3])
        : "r"(a[0]), "r"(a[1]), "r"(a[2]), "r"(a[3]), "r"(b[0]), "r"(b[1]));
}

// one 32-wide K chunk: warp tile 64x32 (4 mt x 4 nt). A cvt optional (pre-rounded
// activations skip it); B (raw fp32 weights) always rna-converted.
template<bool CVTA>
__device__ __forceinline__ void mma_chunk(const float* __restrict__ sA,
                                          const float* __restrict__ sB,
                                          float acc[4][4][4], int g, int t, int mw, int nw) {
#pragma unroll
    for (int ks = 0; ks < 4; ks++) {
        int k8 = ks * 8;
        unsigned a[4][4], b[4][2];
#pragma unroll
        for (int mt = 0; mt < 4; mt++) {
            int r = mw + mt * 16 + g;
            float a0 = sA[r * AS_STRIDE + k8 + t];
            float a1 = sA[(r + 8) * AS_STRIDE + k8 + t];
            float a2 = sA[r * AS_STRIDE + k8 + t + 4];
            float a3 = sA[(r + 8) * AS_STRIDE + k8 + t + 4];
            if (CVTA) {
                a[mt][0] = cvt_tf32(a0); a[mt][1] = cvt_tf32(a1);
                a[mt][2] = cvt_tf32(a2); a[mt][3] = cvt_tf32(a3);
            } else {
                a[mt][0] = __float_as_uint(a0); a[mt][1] = __float_as_uint(a1);
                a[mt][2] = __float_as_uint(a2); a[mt][3] = __float_as_uint(a3);
            }
        }
#pragma unroll
        for (int nt = 0; nt < 4; nt++) {
            int cn = nw + nt * 8 + g;
            b[nt][0] = cvt_tf32(sB[(k8 + t) * BS_STRIDE + cn]);
            b[nt][1] = cvt_tf32(sB[(k8 + t + 4) * BS_STRIDE + cn]);
        }
#pragma unroll
        for (int mt = 0; mt < 4; mt++)
#pragma unroll
            for (int nt = 0; nt < 4; nt++)
                mma8(acc[mt][nt], a[mt], b[nt]);
    }
}

// ---------------- LayerNorm ----------------------------------------------------
// which==0 -> g_h (tf32-rounded: qkv reads it raw); which==1 -> g_h2 (exact fp32
// so the gate argmax is unperturbed; ffn1 converts on the fragment path)
__global__ void ln_kernel(const float* __restrict__ x, const float* __restrict__ gw,
                          const float* __restrict__ gb, int which) {
    float* out = which ? g_h2 : g_h;
    int row = blockIdx.x, tid = threadIdx.x;
    const float* xp = x + (size_t)row * DD;
    float v0 = xp[tid], v1 = xp[tid + 256], v2 = xp[tid + 512];
    float s = v0 + v1 + v2;
    float s2 = v0 * v0 + v1 * v1 + v2 * v2;
#pragma unroll
    for (int o = 16; o; o >>= 1) {
        s  += __shfl_xor_sync(0xffffffffu, s, o);
        s2 += __shfl_xor_sync(0xffffffffu, s2, o);
    }
    __shared__ float r1[8], r2[8];
    if ((tid & 31) == 0) { r1[tid >> 5] = s; r2[tid >> 5] = s2; }
    __syncthreads();
    s = 0.f; s2 = 0.f;
#pragma unroll
    for (int i = 0; i < 8; i++) { s += r1[i]; s2 += r2[i]; }
    float mu = s * (1.f / DD);
    float var = s2 * (1.f / DD) - mu * mu;
    float rs = rsqrtf(var + 1e-5f);
    float* op = out + (size_t)row * DD;
    float o0 = (v0 - mu) * rs * gw[tid]       + gb[tid];
    float o1 = (v1 - mu) * rs * gw[tid + 256] + gb[tid + 256];
    float o2 = (v2 - mu) * rs * gw[tid + 512] + gb[tid + 512];
    if (which == 0) { o0 = tf32f(o0); o1 = tf32f(o1); o2 = tf32f(o2); }
    op[tid] = o0; op[tid + 256] = o1; op[tid + 512] = o2;
}

// ---------------- QKV gemm -----------------------------------------------------
// grid (16, 18): y/6 -> matrix, y%6 -> ntile; outputs tf32-rounded.
__global__ __launch_bounds__(256, 2) void qkv_tc(
    const float* __restrict__ Wq, const float* __restrict__ Wk, const float* __restrict__ Wv) {
    extern __shared__ float sm[];
    int tid = threadIdx.x, lane = tid & 31, warp = tid >> 5;
    int g = lane >> 2, t = lane & 3;
    int mw = (warp >> 2) * 64, nw = (warp & 3) * 32;
    int m0 = blockIdx.x * 128;
    int y = blockIdx.y;
    const float* W = (y < 6) ? Wq : (y < 12 ? Wk : Wv);
    float* dst = (y < 6) ? g_q : (y < 12 ? g_k : g_v);
    int n0 = (y % 6) * 128;

    unsigned sbase = (unsigned)__cvta_generic_to_shared(sm);
    const float* arow[4]; unsigned asmo[4];
    const float* brow[4]; unsigned bsmo[4];
#pragma unroll
    for (int i = 0; i < 4; i++) {
        int f = tid + i * 256;
        int r = f >> 3, kq = (f & 7) * 4;
        arow[i] = g_h + (size_t)(m0 + r) * DD + kq;
        asmo[i] = sbase + (r * AS_STRIDE + kq) * 4;
        int kk = f >> 5, nq = (f & 31) * 4;
        int j = n0 + nq;
        brow[i] = W + (size_t)(j >> 6) * DD * HSZ + (j & 63) + kk * HSZ;
        bsmo[i] = sbase + (B_BASE3 + kk * BS_STRIDE + nq) * 4;
    }
    float acc[4][4][4] = {};
    const int NC = DD / 32;  // 24
#pragma unroll
    for (int p = 0; p < 2; p++) {
        int k0 = p * 32;
#pragma unroll
        for (int i = 0; i < 4; i++) cpa16(asmo[i] + p * AS_BUF * 4, arow[i] + k0);
#pragma unroll
        for (int i = 0; i < 4; i++) cpa16(bsmo[i] + p * BS_BUF * 4, brow[i] + k0 * HSZ);
        cp_commit();
    }
#pragma unroll 1
    for (int c = 0; c < NC; c++) {
        if (c + 1 < NC) cp_wait1(); else cp_wait0();
        __syncthreads();
        int buf = c % 3;
        mma_chunk<false>(sm + buf * AS_BUF, sm + B_BASE3 + buf * BS_BUF, acc, g, t, mw, nw);
        if (c + 2 < NC) {
            int k0 = (c + 2) * 32, nb = (c + 2) % 3;
#pragma unroll
            for (int i = 0; i < 4; i++) cpa16(asmo[i] + nb * AS_BUF * 4, arow[i] + k0);
#pragma unroll
            for (int i = 0; i < 4; i++) cpa16(bsmo[i] + nb * BS_BUF * 4, brow[i] + k0 * HSZ);
            cp_commit();
        }
    }
#pragma unroll
    for (int mt = 0; mt < 4; mt++) {
#pragma unroll
        for (int nt = 0; nt < 4; nt++) {
            int col = nw + nt * 8 + 2 * t;
            int j = n0 + col, h = j >> 6, s_ = j & 63;
#pragma unroll
            for (int half = 0; half < 2; half++) {
                int m = m0 + mw + mt * 16 + g + half * 8;
                int b_ = m >> 10, t_ = m & 1023;
                float2 v = make_float2(tf32f(acc[mt][nt][half * 2]),
                                       tf32f(acc[mt][nt][half * 2 + 1]));
                *(float2*)(dst + (((size_t)(b_ * HH + h) * TT + t_) << 6) + s_) = v;
            }
        }
    }
}

// ---------------- tensor-core flash attention ---------------------------------
// grid (8, 12, 2) -> (qtile, head, batch), 256 thr (8 warps x 16 rows).
// Q pre-scaled+rounded into smem; K/V double-buffered via cp.async; per-warp
// row stats; P staged through warp-private psh rows (tf32-rounded).
__global__ __launch_bounds__(256) void attn_tc() {
    extern __shared__ float sm[];
    int tid = threadIdx.x, lane = tid & 31, w = tid >> 5;
    int g = lane >> 2, t = lane & 3;
    int qt = (int)gridDim.x - 1 - (int)blockIdx.x;   // heavy tiles first
    int h = blockIdx.y, b = blockIdx.z;
    int m0 = qt * 128;
    const float scale = rsqrtf((float)DD);
    const float* qbase = g_q + ((size_t)(b * HH + h) * TT + m0) * HSZ;
    const float* kbase = g_k + (size_t)(b * HH + h) * TT * HSZ;
    const float* vbase = g_v + (size_t)(b * HH + h) * TT * HSZ;
    unsigned sbase = (unsigned)__cvta_generic_to_shared(sm);

    int ntiles = 2 * (qt + 1);
    int r_ = tid >> 4, c_ = (tid & 15) * 4;
    // prologue: issue K/V tile 0
    {
        const float* kp = kbase;
        const float* vp = vbase;
#pragma unroll
        for (int i = 0; i < 4; i++) {
            int rr = r_ + i * 16;
            cpa16(sbase + (AK + rr * KS_STR + c_) * 4, kp + rr * HSZ + c_);
            cpa16(sbase + (AV + rr * VS_STR + c_) * 4, vp + rr * HSZ + c_);
        }
        cp_commit();
    }
    // load Q (scale + tf32 round)
#pragma unroll
    for (int i = 0; i < 8; i++) {
        int f = tid + i * 256;
        int rr = f >> 4, cc = (f & 15) * 4;
        float4 v = *(const float4*)(qbase + (size_t)rr * HSZ + cc);
        v.x = tf32f(v.x * scale); v.y = tf32f(v.y * scale);
        v.z = tf32f(v.z * scale); v.w = tf32f(v.w * scale);
        *(float4*)&sm[AQ + rr * QS_STR + cc] = v;
    }

    int mw = w * 16;
    int qrow0 = m0 + mw + g, qrow1 = qrow0 + 8;
    float m0s = -1e30f, m1s = -1e30f, l0s = 0.f, l1s = 0.f;
    float acc_o[8][4] = {};

#pragma unroll 1
    for (int kt = 0; kt < ntiles; kt++) {
        cp_wait0();
        __syncthreads();            // K/V tile kt (and Q on kt==0) resident
        int buf = kt & 1;
        // issue next tile into the other buffer (fully consumed last iteration)
        if (kt + 1 < ntiles) {
            const float* kp = kbase + (size_t)(kt + 1) * 64 * HSZ;
            const float* vp = vbase + (size_t)(kt + 1) * 64 * HSZ;
            int ob = buf ^ 1;
#pragma unroll
            for (int i = 0; i < 4; i++) {
                int rr = r_ + i * 16;
                cpa16(sbase + (AK + ob * 64 * KS_STR + rr * KS_STR + c_) * 4, kp + rr * HSZ + c_);
                cpa16(sbase + (AV + ob * 64 * VS_STR + rr * VS_STR + c_) * 4, vp + rr * HSZ + c_);
            }
            cp_commit();
        }
        const float* ks_ = sm + AK + buf * 64 * KS_STR;
        const float* vs_ = sm + AV + buf * 64 * VS_STR;

        // ---- S = Q @ K^T  (16x64 per warp) ----
        float s_acc[8][4];
#pragma unroll
        for (int nt = 0; nt < 8; nt++) { s_acc[nt][0] = s_acc[nt][1] = s_acc[nt][2] = s_acc[nt][3] = 0.f; }
#pragma unroll
        for (int k8i = 0; k8i < 8; k8i++) {
            int k8 = k8i * 8;
            unsigned a[4];
            a[0] = __float_as_uint(sm[AQ + (mw + g) * QS_STR + k8 + t]);
            a[1] = __float_as_uint(sm[AQ + (mw + g + 8) * QS_STR + k8 + t]);
            a[2] = __float_as_uint(sm[AQ + (mw + g) * QS_STR + k8 + t + 4]);
            a[3] = __float_as_uint(sm[AQ + (mw + g + 8) * QS_STR + k8 + t + 4]);
#pragma unroll
            for (int nt = 0; nt < 8; nt++) {
                unsigned bf[2];
                bf[0] = __float_as_uint(ks_[(nt * 8 + g) * KS_STR + k8 + t]);
                bf[1] = __float_as_uint(ks_[(nt * 8 + g) * KS_STR + k8 + t + 4]);
                mma8(s_acc[nt], a, bf);
            }
        }
        // ---- mask + online softmax ----
        int k0 = kt * 64;
        if (kt >= 2 * qt) {   // diagonal tiles need elementwise mask
#pragma unroll
            for (int nt = 0; nt < 8; nt++) {
                int c0 = k0 + nt * 8 + 2 * t, c1 = c0 + 1;
                if (c0 > qrow0) s_acc[nt][0] = -1e30f;
                if (c1 > qrow0) s_acc[nt][1] = -1e30f;
                if (c0 > qrow1) s_acc[nt][2] = -1e30f;
                if (c1 > qrow1) s_acc[nt][3] = -1e30f;
            }
        }
        float mt0 = m0s, mt1 = m1s;
#pragma unroll
        for (int nt = 0; nt < 8; nt++) {
            mt0 = fmaxf(mt0, fmaxf(s_acc[nt][0], s_acc[nt][1]));
            mt1 = fmaxf(mt1, fmaxf(s_acc[nt][2], s_acc[nt][3]));
        }
        mt0 = fmaxf(mt0, __shfl_xor_sync(0xffffffffu, mt0, 1));
        mt0 = fmaxf(mt0, __shfl_xor_sync(0xffffffffu, mt0, 2));
        mt1 = fmaxf(mt1, __shfl_xor_sync(0xffffffffu, mt1, 1));
        mt1 = fmaxf(mt1, __shfl_xor_sync(0xffffffffu, mt1, 2));
        float r0 = __expf(m0s - mt0), r1 = __expf(m1s - mt1);
        m0s = mt0; m1s = mt1;
        float ls0 = 0.f, ls1 = 0.f;
#pragma unroll
        for (int nt = 0; nt < 8; nt++) {
            float p0 = __expf(s_acc[nt][0] - mt0);
            float p1 = __expf(s_acc[nt][1] - mt0);
            float p2 = __expf(s_acc[nt][2] - mt1);
            float p3 = __expf(s_acc[nt][3] - mt1);
            ls0 += p0 + p1; ls1 += p2 + p3;
            int cc = nt * 8 + 2 * t;
            *(float2*)&sm[AP + (mw + g) * PS_STR + cc]     = make_float2(tf32f(p0), tf32f(p1));
            *(float2*)&sm[AP + (mw + g + 8) * PS_STR + cc] = make_float2(tf32f(p2), tf32f(p3));
        }
        ls0 += __shfl_xor_sync(0xffffffffu, ls0, 1);
        ls0 += __shfl_xor_sync(0xffffffffu, ls0, 2);
        ls1 += __shfl_xor_sync(0xffffffffu, ls1, 1);
        ls1 += __shfl_xor_sync(0xffffffffu, ls1, 2);
        l0s = l0s * r0 + ls0;
        l1s = l1s * r1 + ls1;
#pragma unroll
        for (int nt = 0; nt < 8; nt++) {
            acc_o[nt][0] *= r0; acc_o[nt][1] *= r0;
            acc_o[nt][2] *= r1; acc_o[nt][3] *= r1;
        }
        __syncwarp();   // psh rows are warp-private; cross-lane visibility only

        // ---- O += P @ V  (16x64 per warp, K=64 keys) ----
#pragma unroll
        for (int k8i = 0; k8i < 8; k8i++) {
            int k8 = k8i * 8;
            unsigned a[4];
            a[0] = __float_as_uint(sm[AP + (mw + g) * PS_STR + k8 + t]);
            a[1] = __float_as_uint(sm[AP + (mw + g + 8) * PS_STR + k8 + t]);
            a[2] = __float_as_uint(sm[AP + (mw + g) * PS_STR + k8 + t + 4]);
            a[3] = __float_as_uint(sm[AP + (mw + g + 8) * PS_STR + k8 + t + 4]);
#pragma unroll
            for (int nt = 0; nt < 8; nt++) {
                unsigned bf[2];
                bf[0] = __float_as_uint(vs_[(k8 + t) * VS_STR + nt * 8 + g]);
                bf[1] = __float_as_uint(vs_[(k8 + t + 4) * VS_STR + nt * 8 + g]);
                mma8(acc_o[nt], a, bf);
            }
        }
        __syncwarp();
    }
    float inv0 = 1.f / l0s, inv1 = 1.f / l1s;
    float* o0 = g_att + ((size_t)(b * TT) + qrow0) * DD + h * HSZ;
    float* o1 = g_att + ((size_t)(b * TT) + qrow1) * DD + h * HSZ;
#pragma unroll
    for (int nt = 0; nt < 8; nt++) {
        int cc = nt * 8 + 2 * t;
        *(float2*)(o0 + cc) = make_float2(tf32f(acc_o[nt][0] * inv0), tf32f(acc_o[nt][1] * inv0));
        *(float2*)(o1 + cc) = make_float2(tf32f(acc_o[nt][2] * inv1), tf32f(acc_o[nt][3] * inv1));
    }
}

// ---------------- output projection + residual ---------------------------------
// grid (16, 6)
__global__ __launch_bounds__(256, 2) void proj_tc(
    const float* __restrict__ Wp, const float* __restrict__ bp,
    const float* __restrict__ x, float* __restrict__ out) {
    extern __shared__ float sm[];
    int tid = threadIdx.x, lane = tid & 31, warp = tid >> 5;
    int g = lane >> 2, t = lane & 3;
    int mw = (warp >> 2) * 64, nw = (warp & 3) * 32;
    int m0 = blockIdx.x * 128;
    int n0 = blockIdx.y * 128;

    unsigned sbase = (unsigned)__cvta_generic_to_shared(sm);
    const float* arow[4]; unsigned asmo[4];
    const float* brow[4]; unsigned bsmo[4];
#pragma unroll
    for (int i = 0; i < 4; i++) {
        int f = tid + i * 256;
        int r = f >> 3, kq = (f & 7) * 4;
        arow[i] = g_att + (size_t)(m0 + r) * DD + kq;
        asmo[i] = sbase + (r * AS_STRIDE + kq) * 4;
        int kk = f >> 5, nq = (f & 31) * 4;
        brow[i] = Wp + (size_t)kk * DD + n0 + nq;
        bsmo[i] = sbase + (B_BASE3 + kk * BS_STRIDE + nq) * 4;
    }
    float acc[4][4][4] = {};
    const int NC = DD / 32;
#pragma unroll
    for (int p = 0; p < 2; p++) {
        int k0 = p * 32;
#pragma unroll
        for (int i = 0; i < 4; i++) cpa16(asmo[i] + p * AS_BUF * 4, arow[i] + k0);
#pragma unroll
        for (int i = 0; i < 4; i++) cpa16(bsmo[i] + p * BS_BUF * 4, brow[i] + (size_t)k0 * DD);
        cp_commit();
    }
#pragma unroll 1
    for (int c = 0; c < NC; c++) {
        if (c + 1 < NC) cp_wait1(); else cp_wait0();
        __syncthreads();
        int buf = c % 3;
        mma_chunk<false>(sm + buf * AS_BUF, sm + B_BASE3 + buf * BS_BUF, acc, g, t, mw, nw);
        if (c + 2 < NC) {
            int k0 = (c + 2) * 32, nb = (c + 2) % 3;
#pragma unroll
            for (int i = 0; i < 4; i++) cpa16(asmo[i] + nb * AS_BUF * 4, arow[i] + k0);
#pragma unroll
            for (int i = 0; i < 4; i++) cpa16(bsmo[i] + nb * BS_BUF * 4, brow[i] + (size_t)k0 * DD);
            cp_commit();
        }
    }
#pragma unroll
    for (int mt = 0; mt < 4; mt++) {
#pragma unroll
        for (int nt = 0; nt < 4; nt++) {
            int col = n0 + nw + nt * 8 + 2 * t;
#pragma unroll
            for (int half = 0; half < 2; half++) {
                int m = m0 + mw + mt * 16 + g + half * 8;
                size_t idx = (size_t)m * DD + col;
                out[idx]     = acc[mt][nt][half * 2]     + bp[col]     + x[idx];
                out[idx + 1] = acc[mt][nt][half * 2 + 1] + bp[col + 1] + x[idx + 1];
            }
        }
    }
}

// ---------------- MoE gate + routing -------------------------------------------
__global__ void moe_zero() { int t = threadIdx.x; if (t < EE) { g_cnt[t] = 0; g_cur[t] = 0; } }

__global__ void gate_kernel(const float* __restrict__ Wg) {
    int gtid = blockIdx.x * blockDim.x + threadIdx.x;
    int warp = gtid >> 5, lane = gtid & 31;
    if (warp >= NN) return;
    const float* hp = g_h2 + (size_t)warp * DD;
    float best = -1e30f; int bi = 0;
    for (int e = 0; e < EE; e++) {
        float s = 0.f;
        for (int i = lane; i < DD; i += 32) s += hp[i] * Wg[i * EE + e];
#pragma unroll
        for (int o = 16; o; o >>= 1) s += __shfl_xor_sync(0xffffffffu, s, o);
        if (s > best) { best = s; bi = e; }
    }
    if (lane == 0) { g_sel[warp] = bi; atomicAdd(&g_cnt[bi], 1); }
}

__global__ void moe_scan() {
    if (threadIdx.x == 0) {
        int o = 0;
        for (int e = 0; e < EE; e++) { g_off[e] = o; o += ((g_cnt[e] + 127) >> 7) << 7; }
        g_off[EE] = o;
    }
}
__global__ void moe_scatter() {
    int n = blockIdx.x * 256 + threadIdx.x;
    if (n < NN) {
        int e = g_sel[n];
        int p = atomicAdd(&g_cur[e], 1);
        g_perm[g_off[e] + p] = n;
    }
}

// ---------------- expert FFN1: hid = relu(h2[perm] @ W1[e] + b1[e]) ------------
// grid (24, 24); A (g_h2) is exact fp32 -> CVTA=true; output tf32-rounded.
__global__ __launch_bounds__(256, 2) void ffn1_tc(const float* __restrict__ W1,
                                                  const float* __restrict__ b1) {
    int row0 = blockIdx.x * 128;
    if (row0 >= g_off[EE]) return;
    int e = 0;
#pragma unroll
    for (int i = 1; i < EE; i++) if (row0 >= g_off[i]) e = i;
    int valid = g_cnt[e] - (row0 - g_off[e]);
    if (valid > 128) valid = 128;
    extern __shared__ float sm[];
    __shared__ int toks[128];
    int tid = threadIdx.x, lane = tid & 31, warp = tid >> 5;
    int g = lane >> 2, t = lane & 3;
    int mw = (warp >> 2) * 64, nw = (warp & 3) * 32;
    if (tid < 128) toks[tid] = (tid < valid) ? g_perm[row0 + tid] : g_perm[row0];
    __syncthreads();
    int n0 = blockIdx.y * 128;
    const float* wb = W1 + (size_t)e * DD * DFF;

    unsigned sbase = (unsigned)__cvta_generic_to_shared(sm);
    const float* arow[4]; unsigned asmo[4];
    const float* brow[4]; unsigned bsmo[4];
#pragma unroll
    for (int i = 0; i < 4; i++) {
        int f = tid + i * 256;
        int r = f >> 3, kq = (f & 7) * 4;
        arow[i] = g_h2 + (size_t)toks[r] * DD + kq;
        asmo[i] = sbase + (r * AS_STRIDE + kq) * 4;
        int kk = f >> 5, nq = (f & 31) * 4;
        brow[i] = wb + (size_t)kk * DFF + n0 + nq;
        bsmo[i] = sbase + (B_BASE3 + kk * BS_STRIDE + nq) * 4;
    }
    float acc[4][4][4] = {};
    const int NC = DD / 32;
#pragma unroll
    for (int p = 0; p < 2; p++) {
        int k0 = p * 32;
#pragma unroll
        for (int i = 0; i < 4; i++) cpa16(asmo[i] + p * AS_BUF * 4, arow[i] + k0);
#pragma unroll
        for (int i = 0; i < 4; i++) cpa16(bsmo[i] + p * BS_BUF * 4, brow[i] + (size_t)k0 * DFF);
        cp_commit();
    }
#pragma unroll 1
    for (int c = 0; c < NC; c++) {
        if (c + 1 < NC) cp_wait1(); else cp_wait0();
        __syncthreads();
        int buf = c % 3;
        mma_chunk<true>(sm + buf * AS_BUF, sm + B_BASE3 + buf * BS_BUF, acc, g, t, mw, nw);
        if (c + 2 < NC) {
            int k0 = (c + 2) * 32, nb = (c + 2) % 3;
#pragma unroll
            for (int i = 0; i < 4; i++) cpa16(asmo[i] + nb * AS_BUF * 4, arow[i] + k0);
#pragma unroll
            for (int i = 0; i < 4; i++) cpa16(bsmo[i] + nb * BS_BUF * 4, brow[i] + (size_t)k0 * DFF);
            cp_commit();
        }
    }
#pragma unroll
    for (int mt = 0; mt < 4; mt++) {
#pragma unroll
        for (int nt = 0; nt < 4; nt++) {
            int col = n0 + nw + nt * 8 + 2 * t;
#pragma unroll
            for (int half = 0; half < 2; half++) {
                int lr = mw + mt * 16 + g + half * 8;
                if (lr < valid) {
                    float v0 = acc[mt][nt][half * 2]     + b1[(size_t)e * DFF + col];
                    float v1 = acc[mt][nt][half * 2 + 1] + b1[(size_t)e * DFF + col + 1];
                    float2 v = make_float2(tf32f(v0 > 0.f ? v0 : 0.f),
                                           tf32f(v1 > 0.f ? v1 : 0.f));
                    *(float2*)(g_hid + (size_t)(row0 + lr) * DFF + col) = v;
                }
            }
        }
    }
}

// ---------------- expert FFN2: out[tok] += hid @ W2[e] + b2[e] -----------------
// grid (24, 6), K = 3072; A (g_hid) pre-rounded -> CVTA=false.
__global__ __launch_bounds__(256, 2) void ffn2_tc(const float* __restrict__ W2,
                                                  const float* __restrict__ b2,
                                                  float* __restrict__ out) {
    int row0 = blockIdx.x * 128;
    if (row0 >= g_off[EE]) return;
    int e = 0;
#pragma unroll
    for (int i = 1; i < EE; i++) if (row0 >= g_off[i]) e = i;
    int valid = g_cnt[e] - (row0 - g_off[e]);
    if (valid > 128) valid = 128;
    extern __shared__ float sm[];
    __shared__ int toks[128];
    int tid = threadIdx.x, lane = tid & 31, warp = tid >> 5;
    int g = lane >> 2, t = lane & 3;
    int mw = (warp >> 2) * 64, nw = (warp & 3) * 32;
    if (tid < 128) toks[tid] = (tid < valid) ? g_perm[row0 + tid] : 0;
    __syncthreads();
    int n0 = blockIdx.y * 128;
    const float* wb = W2 + (size_t)e * DFF * DD;

    unsigned sbase = (unsigned)__cvta_generic_to_shared(sm);
    const float* arow[4]; unsigned asmo[4];
    const float* brow[4]; unsigned bsmo[4];
#pragma unroll
    for (int i = 0; i < 4; i++) {
        int f = tid + i * 256;
        int r = f >> 3, kq = (f & 7) * 4;
        arow[i] = g_hid + (size_t)(row0 + r) * DFF + kq;
        asmo[i] = sbase + (r * AS_STRIDE + kq) * 4;
        int kk = f >> 5, nq = (f & 31) * 4;
        brow[i] = wb + (size_t)kk * DD + n0 + nq;
        bsmo[i] = sbase + (B_BASE3 + kk * BS_STRIDE + nq) * 4;
    }
    float acc[4][4][4] = {};
    const int NC = DFF / 32;   // 96
#pragma unroll
    for (int p = 0; p < 2; p++) {
        int k0 = p * 32;
#pragma unroll
        for (int i = 0; i < 4; i++) cpa16(asmo[i] + p * AS_BUF * 4, arow[i] + k0);
#pragma unroll
        for (int i = 0; i < 4; i++) cpa16(bsmo[i] + p * BS_BUF * 4, brow[i] + (size_t)k0 * DD);
        cp_commit();
    }
#pragma unroll 1
    for (int c = 0; c < NC; c++) {
        if (c + 1 < NC) cp_wait1(); else cp_wait0();
        __syncthreads();
        int buf = c % 3;
        mma_chunk<false>(sm + buf * AS_BUF, sm + B_BASE3 + buf * BS_BUF, acc, g, t, mw, nw);
        if (c + 2 < NC) {
            int k0 = (c + 2) * 32, nb = (c + 2) % 3;
#pragma unroll
            for (int i = 0; i < 4; i++) cpa16(asmo[i] + nb * AS_BUF * 4, arow[i] + k0);
#pragma unroll
            for (int i = 0; i < 4; i++) cpa16(bsmo[i] + nb * BS_BUF * 4, brow[i] + (size_t)k0 * DD);
            cp_commit();
        }
    }
#pragma unroll
    for (int mt = 0; mt < 4; mt++) {
#pragma unroll
        for (int nt = 0; nt < 4; nt++) {
            int col = n0 + nw + nt * 8 + 2 * t;
#pragma unroll
            for (int half = 0; half < 2; half++) {
                int lr = mw + mt * 16 + g + half * 8;
                if (lr < valid) {
                    int tok = toks[lr];
                    size_t idx = (size_t)tok * DD + col;
                    out[idx]     += acc[mt][nt][half * 2]     + b2[(size_t)e * DD + col];
                    out[idx + 1] += acc[mt][nt][half * 2 + 1] + b2[(size_t)e * DD + col + 1];
                }
            }
        }
    }
}

// ---------------- launch -------------------------------------------------------
extern "C" void kernel_launch(void* const* d_in, const int* in_sizes, int n_in,
                              void* d_out, int out_size) {
    const float* x     = (const float*)d_in[0];
    const float* ln1_g = (const float*)d_in[1];
    const float* ln1_b = (const float*)d_in[2];
    const float* ln2_g = (const float*)d_in[3];
    const float* ln2_b = (const float*)d_in[4];
    const float* Wq    = (const float*)d_in[5];
    const float* Wk    = (const float*)d_in[6];
    const float* Wv    = (const float*)d_in[7];
    const float* Wp    = (const float*)d_in[8];
    const float* bp    = (const float*)d_in[9];
    const float* Wg    = (const float*)d_in[10];
    const float* W1    = (const float*)d_in[11];
    const float* b1    = (const float*)d_in[12];
    const float* W2    = (const float*)d_in[13];
    const float* b2    = (const float*)d_in[14];
    float* out = (float*)d_out;

    const int smem_g = SMEM_G_FLOATS * 4;        // 107520
    const int smem_a = ATT_SMEM_FLOATS * 4;      // 141312
    static bool attr_set = false;
    if (!attr_set) {
        cudaFuncSetAttribute(qkv_tc,  cudaFuncAttributeMaxDynamicSharedMemorySize, smem_g);
        cudaFuncSetAttribute(proj_tc, cudaFuncAttributeMaxDynamicSharedMemorySize, smem_g);
        cudaFuncSetAttribute(ffn1_tc, cudaFuncAttributeMaxDynamicSharedMemorySize, smem_g);
        cudaFuncSetAttribute(ffn2_tc, cudaFuncAttributeMaxDynamicSharedMemorySize, smem_g);
        cudaFuncSetAttribute(attn_tc, cudaFuncAttributeMaxDynamicSharedMemorySize, smem_a);
        attr_set = true;
    }

    ln_kernel<<<NN, 256>>>(x, ln1_g, ln1_b, 0);
    qkv_tc<<<dim3(NN / 128, 18), 256, smem_g>>>(Wq, Wk, Wv);
    attn_tc<<<dim3(TT / 128, HH, BB), 256, smem_a>>>();
    proj_tc<<<dim3(NN / 128, DD / 128), 256, smem_g>>>(Wp, bp, x, out);
    ln_kernel<<<NN, 256>>>(out, ln2_g, ln2_b, 1);
    moe_zero<<<1, 32>>>();
    gate_kernel<<<NN * 32 / 256, 256>>>(Wg);
    moe_scan<<<1, 1>>>();
    moe_scatter<<<NN / 256, 256>>>();
    ffn1_tc<<<dim3(NPAD / 128, DFF / 128), 256, smem_g>>>(W1, b1);
    ffn2_tc<<<dim3(NPAD / 128, DD / 128), 256, smem_g>>>(W2, b2, out);
}

// round 13
// speedup vs baseline: 3.7282x; 1.0006x over previous
#include <cuda_runtime.h>
#include <cstdint>

// Problem dims
#define BB 2
#define TT 1024
#define DD 768
#define HH 12
#define HSZ 64
#define EE 8
#define DFF 3072
#define NN 2048
#define NPAD 3072

// GEMM tiling (3-stage pipeline)
#define AS_STRIDE 36                  // 36j mod 32 = 4j -> LDSM rows conflict-free
#define BS_STRIDE 136
#define AS_BUF (128 * AS_STRIDE)
#define BS_BUF (32 * BS_STRIDE)
#define B_BASE3 (3 * AS_BUF)
#define SMEM_G_FLOATS (3 * (AS_BUF + BS_BUF))   // 26880 floats = 107520 B

// Attention smem layout (floats)
#define QS_STR 68
#define KS_STR 68
#define VS_STR 72
#define PS_STR 68
#define AQ 0
#define AK (128 * QS_STR)
#define AV (AK + 2 * 64 * KS_STR)
#define AP (AV + 2 * 64 * VS_STR)
#define ATT_SMEM_FLOATS (AP + 128 * PS_STR)     // 35328 floats = 141312 B

// ---------------- scratch ------------------------------------------------------
__device__ float g_h[NN * DD];
__device__ float g_q[NN * DD];
__device__ float g_k[NN * DD];
__device__ float g_v[NN * DD];
__device__ float g_att[NN * DD];
__device__ float g_h2[NN * DD];
__device__ float g_hid[NPAD * DFF];
__device__ int   g_sel[NN];
__device__ int   g_cnt[EE];
__device__ int   g_cur[EE];
__device__ int   g_off[EE + 1];
__device__ int   g_perm[NPAD];

// ---------------- helpers ------------------------------------------------------
__device__ __forceinline__ void cpa16(unsigned s, const float* g) {
    asm volatile("cp.async.ca.shared.global [%0], [%1], 16;\n" :: "r"(s), "l"(g));
}
__device__ __forceinline__ void cp_commit() { asm volatile("cp.async.commit_group;\n"); }
__device__ __forceinline__ void cp_wait1() { asm volatile("cp.async.wait_group 1;\n"); }
__device__ __forceinline__ void cp_wait0() { asm volatile("cp.async.wait_group 0;\n"); }

__device__ __forceinline__ unsigned cvt_tf32(float v) {
    unsigned r;
    asm("cvt.rna.tf32.f32 %0, %1;" : "=r"(r) : "f"(v));
    return r;
}
__device__ __forceinline__ float tf32f(float v) { return __uint_as_float(cvt_tf32(v)); }

// ldmatrix x4: four 8x8 b16 tiles (= 8 rows x 4 f32); per-lane row addresses.
__device__ __forceinline__ void ldsm4(unsigned& r0, unsigned& r1, unsigned& r2, unsigned& r3,
                                      unsigned addr) {
    asm volatile("ldmatrix.sync.aligned.m8n8.x4.shared.b16 {%0,%1,%2,%3}, [%4];"
        : "=r"(r0), "=r"(r1), "=r"(r2), "=r"(r3) : "r"(addr));
}

__device__ __forceinline__ void mma8(float* c, const unsigned* a, const unsigned* b) {
    asm volatile(
        "mma.sync.aligned.m16n8k8.row.col.f32.tf32.tf32.f32 "
        "{%0,%1,%2,%3},{%4,%5,%6,%7},{%8,%9},{%0,%1,%2,%3};\n"
        : "+f"(c[0]), "+f"(c[1]), "+f"(c[2]), "+f"(c[3])
        : "r"(a[0]), "r"(a[1]), "r"(a[2]), "r"(a[3]), "r"(b[0]), "r"(b[1]));
}

// A-fragment lane address offset (bytes, excl. tile row base / k8):
// lanes 0-7: tile0 rows(+0),col k8 | 8-15: tile1 rows(+8) | 16-23: tile2 col +4 | 24-31: tile3 +8,+4
__device__ __forceinline__ unsigned afrag_lane_off(int lane, int stride_f) {
    int row_l = (lane & 7) + ((lane >> 3) & 1) * 8;
    int col_l = (lane >> 4) * 4;
    return (unsigned)((row_l * stride_f + col_l) * 4);
}
// B-fragment (row-major [n][k] smem) lane offset: tiles = (n0..+7,k8),(n0..+7,k8+4),(n0+8..,k8),(n0+8..,k8+4)
__device__ __forceinline__ unsigned bfrag_lane_off(int lane, int stride_f) {
    int row_l = (lane & 7) + (lane >> 4) * 8;
    int col_l = ((lane >> 3) & 1) * 4;
    return (unsigned)((row_l * stride_f + col_l) * 4);
}

// one 32-wide K chunk: warp tile 64x32 (4 mt x 4 nt). A via LDSM (optional rna cvt),
// B (weights, [k][n] smem) scalar + rna cvt.
template<bool CVTA>
__device__ __forceinline__ void mma_chunk(unsigned aAddr, const float* __restrict__ sB,
                                          float acc[4][4][4], int g, int t, int mw, int nw) {
#pragma unroll
    for (int ks = 0; ks < 4; ks++) {
        int k8 = ks * 8;
        unsigned a[4][4], b[4][2];
#pragma unroll
        for (int mt = 0; mt < 4; mt++) {
            unsigned ad = aAddr + (unsigned)(((mw + mt * 16) * AS_STRIDE + k8) * 4);
            ldsm4(a[mt][0], a[mt][1], a[mt][2], a[mt][3], ad);
            if (CVTA) {
                a[mt][0] = cvt_tf32(__uint_as_float(a[mt][0]));
                a[mt][1] = cvt_tf32(__uint_as_float(a[mt][1]));
                a[mt][2] = cvt_tf32(__uint_as_float(a[mt][2]));
                a[mt][3] = cvt_tf32(__uint_as_float(a[mt][3]));
            }
        }
#pragma unroll
        for (int nt = 0; nt < 4; nt++) {
            int cn = nw + nt * 8 + g;
            b[nt][0] = cvt_tf32(sB[(k8 + t) * BS_STRIDE + cn]);
            b[nt][1] = cvt_tf32(sB[(k8 + t + 4) * BS_STRIDE + cn]);
        }
#pragma unroll
        for (int mt = 0; mt < 4; mt++)
#pragma unroll
            for (int nt = 0; nt < 4; nt++)
                mma8(acc[mt][nt], a[mt], b[nt]);
    }
}

// ---------------- LayerNorm ----------------------------------------------------
__global__ void ln_kernel(const float* __restrict__ x, const float* __restrict__ gw,
                          const float* __restrict__ gb, int which) {
    float* out = which ? g_h2 : g_h;
    int row = blockIdx.x, tid = threadIdx.x;
    const float* xp = x + (size_t)row * DD;
    float v0 = xp[tid], v1 = xp[tid + 256], v2 = xp[tid + 512];
    float s = v0 + v1 + v2;
    float s2 = v0 * v0 + v1 * v1 + v2 * v2;
#pragma unroll
    for (int o = 16; o; o >>= 1) {
        s  += __shfl_xor_sync(0xffffffffu, s, o);
        s2 += __shfl_xor_sync(0xffffffffu, s2, o);
    }
    __shared__ float r1[8], r2[8];
    if ((tid & 31) == 0) { r1[tid >> 5] = s; r2[tid >> 5] = s2; }
    __syncthreads();
    s = 0.f; s2 = 0.f;
#pragma unroll
    for (int i = 0; i < 8; i++) { s += r1[i]; s2 += r2[i]; }
    float mu = s * (1.f / DD);
    float var = s2 * (1.f / DD) - mu * mu;
    float rs = rsqrtf(var + 1e-5f);
    float* op = out + (size_t)row * DD;
    float o0 = (v0 - mu) * rs * gw[tid]       + gb[tid];
    float o1 = (v1 - mu) * rs * gw[tid + 256] + gb[tid + 256];
    float o2 = (v2 - mu) * rs * gw[tid + 512] + gb[tid + 512];
    if (which == 0) { o0 = tf32f(o0); o1 = tf32f(o1); o2 = tf32f(o2); }
    op[tid] = o0; op[tid + 256] = o1; op[tid + 512] = o2;
}

// ---------------- QKV gemm -----------------------------------------------------
__global__ __launch_bounds__(256, 2) void qkv_tc(
    const float* __restrict__ Wq, const float* __restrict__ Wk, const float* __restrict__ Wv) {
    extern __shared__ float sm[];
    int tid = threadIdx.x, lane = tid & 31, warp = tid >> 5;
    int g = lane >> 2, t = lane & 3;
    int mw = (warp >> 2) * 64, nw = (warp & 3) * 32;
    int m0 = blockIdx.x * 128;
    int y = blockIdx.y;
    const float* W = (y < 6) ? Wq : (y < 12 ? Wk : Wv);
    float* dst = (y < 6) ? g_q : (y < 12 ? g_k : g_v);
    int n0 = (y % 6) * 128;

    unsigned sbase = (unsigned)__cvta_generic_to_shared(sm);
    unsigned aLane = sbase + afrag_lane_off(lane, AS_STRIDE);
    const float* arow[4]; unsigned asmo[4];
    const float* brow[4]; unsigned bsmo[4];
#pragma unroll
    for (int i = 0; i < 4; i++) {
        int f = tid + i * 256;
        int r = f >> 3, kq = (f & 7) * 4;
        arow[i] = g_h + (size_t)(m0 + r) * DD + kq;
        asmo[i] = sbase + (r * AS_STRIDE + kq) * 4;
        int kk = f >> 5, nq = (f & 31) * 4;
        int j = n0 + nq;
        brow[i] = W + (size_t)(j >> 6) * DD * HSZ + (j & 63) + kk * HSZ;
        bsmo[i] = sbase + (B_BASE3 + kk * BS_STRIDE + nq) * 4;
    }
    float acc[4][4][4] = {};
    const int NC = DD / 32;  // 24
#pragma unroll
    for (int p = 0; p < 2; p++) {
        int k0 = p * 32;
#pragma unroll
        for (int i = 0; i < 4; i++) cpa16(asmo[i] + p * AS_BUF * 4, arow[i] + k0);
#pragma unroll
        for (int i = 0; i < 4; i++) cpa16(bsmo[i] + p * BS_BUF * 4, brow[i] + k0 * HSZ);
        cp_commit();
    }
#pragma unroll 1
    for (int c = 0; c < NC; c++) {
        if (c + 1 < NC) cp_wait1(); else cp_wait0();
        __syncthreads();
        int buf = c % 3;
        mma_chunk<false>(aLane + buf * AS_BUF * 4, sm + B_BASE3 + buf * BS_BUF, acc, g, t, mw, nw);
        if (c + 2 < NC) {
            int k0 = (c + 2) * 32, nb = (c + 2) % 3;
#pragma unroll
            for (int i = 0; i < 4; i++) cpa16(asmo[i] + nb * AS_BUF * 4, arow[i] + k0);
#pragma unroll
            for (int i = 0; i < 4; i++) cpa16(bsmo[i] + nb * BS_BUF * 4, brow[i] + k0 * HSZ);
            cp_commit();
        }
    }
#pragma unroll
    for (int mt = 0; mt < 4; mt++) {
#pragma unroll
        for (int nt = 0; nt < 4; nt++) {
            int col = nw + nt * 8 + 2 * t;
            int j = n0 + col, h = j >> 6, s_ = j & 63;
#pragma unroll
            for (int half = 0; half < 2; half++) {
                int m = m0 + mw + mt * 16 + g + half * 8;
                int b_ = m >> 10, t_ = m & 1023;
                float2 v = make_float2(tf32f(acc[mt][nt][half * 2]),
                                       tf32f(acc[mt][nt][half * 2 + 1]));
                *(float2*)(dst + (((size_t)(b_ * HH + h) * TT + t_) << 6) + s_) = v;
            }
        }
    }
}

// ---------------- tensor-core flash attention ---------------------------------
__global__ __launch_bounds__(256) void attn_tc() {
    extern __shared__ float sm[];
    int tid = threadIdx.x, lane = tid & 31, w = tid >> 5;
    int g = lane >> 2, t = lane & 3;
    int qt = (int)gridDim.x - 1 - (int)blockIdx.x;
    int h = blockIdx.y, b = blockIdx.z;
    int m0 = qt * 128;
    const float scale = rsqrtf((float)DD);
    const float* qbase = g_q + ((size_t)(b * HH + h) * TT + m0) * HSZ;
    const float* kbase = g_k + (size_t)(b * HH + h) * TT * HSZ;
    const float* vbase = g_v + (size_t)(b * HH + h) * TT * HSZ;
    unsigned sbase = (unsigned)__cvta_generic_to_shared(sm);
    unsigned qLane = sbase + AQ * 4 + afrag_lane_off(lane, QS_STR);
    unsigned pLane = sbase + AP * 4 + afrag_lane_off(lane, PS_STR);
    unsigned kLane = sbase + AK * 4 + bfrag_lane_off(lane, KS_STR);

    int ntiles = 2 * (qt + 1);
    int r_ = tid >> 4, c_ = (tid & 15) * 4;
    {
#pragma unroll
        for (int i = 0; i < 4; i++) {
            int rr = r_ + i * 16;
            cpa16(sbase + (AK + rr * KS_STR + c_) * 4, kbase + rr * HSZ + c_);
            cpa16(sbase + (AV + rr * VS_STR + c_) * 4, vbase + rr * HSZ + c_);
        }
        cp_commit();
    }
#pragma unroll
    for (int i = 0; i < 8; i++) {
        int f = tid + i * 256;
        int rr = f >> 4, cc = (f & 15) * 4;
        float4 v = *(const float4*)(qbase + (size_t)rr * HSZ + cc);
        v.x = tf32f(v.x * scale); v.y = tf32f(v.y * scale);
        v.z = tf32f(v.z * scale); v.w = tf32f(v.w * scale);
        *(float4*)&sm[AQ + rr * QS_STR + cc] = v;
    }

    int mw = w * 16;
    int qrow0 = m0 + mw + g, qrow1 = qrow0 + 8;
    float m0s = -1e30f, m1s = -1e30f, l0s = 0.f, l1s = 0.f;
    float acc_o[8][4] = {};

#pragma unroll 1
    for (int kt = 0; kt < ntiles; kt++) {
        cp_wait0();
        __syncthreads();
        int buf = kt & 1;
        if (kt + 1 < ntiles) {
            const float* kp = kbase + (size_t)(kt + 1) * 64 * HSZ;
            const float* vp = vbase + (size_t)(kt + 1) * 64 * HSZ;
            int ob = buf ^ 1;
#pragma unroll
            for (int i = 0; i < 4; i++) {
                int rr = r_ + i * 16;
                cpa16(sbase + (AK + ob * 64 * KS_STR + rr * KS_STR + c_) * 4, kp + rr * HSZ + c_);
                cpa16(sbase + (AV + ob * 64 * VS_STR + rr * VS_STR + c_) * 4, vp + rr * HSZ + c_);
            }
            cp_commit();
        }
        const float* vs_ = sm + AV + buf * 64 * VS_STR;
        unsigned kBufLane = kLane + (unsigned)(buf * 64 * KS_STR * 4);

        // ---- S = Q @ K^T via LDSM fragments ----
        float s_acc[8][4];
#pragma unroll
        for (int nt = 0; nt < 8; nt++) { s_acc[nt][0] = s_acc[nt][1] = s_acc[nt][2] = s_acc[nt][3] = 0.f; }
#pragma unroll
        for (int k8i = 0; k8i < 8; k8i++) {
            int k8 = k8i * 8;
            unsigned a[4];
            ldsm4(a[0], a[1], a[2], a[3], qLane + (unsigned)((mw * QS_STR + k8) * 4));
#pragma unroll
            for (int p = 0; p < 4; p++) {
                unsigned b0, b1, b2, b3;
                ldsm4(b0, b1, b2, b3, kBufLane + (unsigned)((p * 16 * KS_STR + k8) * 4));
                unsigned bb0[2] = {b0, b1}, bb1[2] = {b2, b3};
                mma8(s_acc[2 * p], a, bb0);
                mma8(s_acc[2 * p + 1], a, bb1);
            }
        }
        // ---- mask + online softmax ----
        int k0 = kt * 64;
        if (kt >= 2 * qt) {
#pragma unroll
            for (int nt = 0; nt < 8; nt++) {
                int c0 = k0 + nt * 8 + 2 * t, c1 = c0 + 1;
                if (c0 > qrow0) s_acc[nt][0] = -1e30f;
                if (c1 > qrow0) s_acc[nt][1] = -1e30f;
                if (c0 > qrow1) s_acc[nt][2] = -1e30f;
                if (c1 > qrow1) s_acc[nt][3] = -1e30f;
            }
        }
        float mt0 = m0s, mt1 = m1s;
#pragma unroll
        for (int nt = 0; nt < 8; nt++) {
            mt0 = fmaxf(mt0, fmaxf(s_acc[nt][0], s_acc[nt][1]));
            mt1 = fmaxf(mt1, fmaxf(s_acc[nt][2], s_acc[nt][3]));
        }
        mt0 = fmaxf(mt0, __shfl_xor_sync(0xffffffffu, mt0, 1));
        mt0 = fmaxf(mt0, __shfl_xor_sync(0xffffffffu, mt0, 2));
        mt1 = fmaxf(mt1, __shfl_xor_sync(0xffffffffu, mt1, 1));
        mt1 = fmaxf(mt1, __shfl_xor_sync(0xffffffffu, mt1, 2));
        float r0 = __expf(m0s - mt0), r1 = __expf(m1s - mt1);
        m0s = mt0; m1s = mt1;
        float ls0 = 0.f, ls1 = 0.f;
#pragma unroll
        for (int nt = 0; nt < 8; nt++) {
            float p0 = __expf(s_acc[nt][0] - mt0);
            float p1 = __expf(s_acc[nt][1] - mt0);
            float p2 = __expf(s_acc[nt][2] - mt1);
            float p3 = __expf(s_acc[nt][3] - mt1);
            ls0 += p0 + p1; ls1 += p2 + p3;
            int cc = nt * 8 + 2 * t;
            *(float2*)&sm[AP + (mw + g) * PS_STR + cc]     = make_float2(tf32f(p0), tf32f(p1));
            *(float2*)&sm[AP + (mw + g + 8) * PS_STR + cc] = make_float2(tf32f(p2), tf32f(p3));
        }
        ls0 += __shfl_xor_sync(0xffffffffu, ls0, 1);
        ls0 += __shfl_xor_sync(0xffffffffu, ls0, 2);
        ls1 += __shfl_xor_sync(0xffffffffu, ls1, 1);
        ls1 += __shfl_xor_sync(0xffffffffu, ls1, 2);
        l0s = l0s * r0 + ls0;
        l1s = l1s * r1 + ls1;
#pragma unroll
        for (int nt = 0; nt < 8; nt++) {
            acc_o[nt][0] *= r0; acc_o[nt][1] *= r0;
            acc_o[nt][2] *= r1; acc_o[nt][3] *= r1;
        }
        __syncwarp();

        // ---- O += P @ V ----
#pragma unroll
        for (int k8i = 0; k8i < 8; k8i++) {
            int k8 = k8i * 8;
            unsigned a[4];
            ldsm4(a[0], a[1], a[2], a[3], pLane + (unsigned)((mw * PS_STR + k8) * 4));
#pragma unroll
            for (int nt = 0; nt < 8; nt++) {
                unsigned bf[2];
                bf[0] = __float_as_uint(vs_[(k8 + t) * VS_STR + nt * 8 + g]);
                bf[1] = __float_as_uint(vs_[(k8 + t + 4) * VS_STR + nt * 8 + g]);
                mma8(acc_o[nt], a, bf);
            }
        }
        __syncwarp();
    }
    float inv0 = 1.f / l0s, inv1 = 1.f / l1s;
    float* o0 = g_att + ((size_t)(b * TT) + qrow0) * DD + h * HSZ;
    float* o1 = g_att + ((size_t)(b * TT) + qrow1) * DD + h * HSZ;
#pragma unroll
    for (int nt = 0; nt < 8; nt++) {
        int cc = nt * 8 + 2 * t;
        *(float2*)(o0 + cc) = make_float2(tf32f(acc_o[nt][0] * inv0), tf32f(acc_o[nt][1] * inv0));
        *(float2*)(o1 + cc) = make_float2(tf32f(acc_o[nt][2] * inv1), tf32f(acc_o[nt][3] * inv1));
    }
}

// ---------------- output projection + residual ---------------------------------
__global__ __launch_bounds__(256, 2) void proj_tc(
    const float* __restrict__ Wp, const float* __restrict__ bp,
    const float* __restrict__ x, float* __restrict__ out) {
    extern __shared__ float sm[];
    int tid = threadIdx.x, lane = tid & 31, warp = tid >> 5;
    int g = lane >> 2, t = lane & 3;
    int mw = (warp >> 2) * 64, nw = (warp & 3) * 32;
    int m0 = blockIdx.x * 128;
    int n0 = blockIdx.y * 128;

    unsigned sbase = (unsigned)__cvta_generic_to_shared(sm);
    unsigned aLane = sbase + afrag_lane_off(lane, AS_STRIDE);
    const float* arow[4]; unsigned asmo[4];
    const float* brow[4]; unsigned bsmo[4];
#pragma unroll
    for (int i = 0; i < 4; i++) {
        int f = tid + i * 256;
        int r = f >> 3, kq = (f & 7) * 4;
        arow[i] = g_att + (size_t)(m0 + r) * DD + kq;
        asmo[i] = sbase + (r * AS_STRIDE + kq) * 4;
        int kk = f >> 5, nq = (f & 31) * 4;
        brow[i] = Wp + (size_t)kk * DD + n0 + nq;
        bsmo[i] = sbase + (B_BASE3 + kk * BS_STRIDE + nq) * 4;
    }
    float acc[4][4][4] = {};
    const int NC = DD / 32;
#pragma unroll
    for (int p = 0; p < 2; p++) {
        int k0 = p * 32;
#pragma unroll
        for (int i = 0; i < 4; i++) cpa16(asmo[i] + p * AS_BUF * 4, arow[i] + k0);
#pragma unroll
        for (int i = 0; i < 4; i++) cpa16(bsmo[i] + p * BS_BUF * 4, brow[i] + (size_t)k0 * DD);
        cp_commit();
    }
#pragma unroll 1
    for (int c = 0; c < NC; c++) {
        if (c + 1 < NC) cp_wait1(); else cp_wait0();
        __syncthreads();
        int buf = c % 3;
        mma_chunk<false>(aLane + buf * AS_BUF * 4, sm + B_BASE3 + buf * BS_BUF, acc, g, t, mw, nw);
        if (c + 2 < NC) {
            int k0 = (c + 2) * 32, nb = (c + 2) % 3;
#pragma unroll
            for (int i = 0; i < 4; i++) cpa16(asmo[i] + nb * AS_BUF * 4, arow[i] + k0);
#pragma unroll
            for (int i = 0; i < 4; i++) cpa16(bsmo[i] + nb * BS_BUF * 4, brow[i] + (size_t)k0 * DD);
            cp_commit();
        }
    }
#pragma unroll
    for (int mt = 0; mt < 4; mt++) {
#pragma unroll
        for (int nt = 0; nt < 4; nt++) {
            int col = n0 + nw + nt * 8 + 2 * t;
#pragma unroll
            for (int half = 0; half < 2; half++) {
                int m = m0 + mw + mt * 16 + g + half * 8;
                size_t idx = (size_t)m * DD + col;
                out[idx]     = acc[mt][nt][half * 2]     + bp[col]     + x[idx];
                out[idx + 1] = acc[mt][nt][half * 2 + 1] + bp[col + 1] + x[idx + 1];
            }
        }
    }
}

// ---------------- MoE gate + routing -------------------------------------------
__global__ void moe_zero() { int t = threadIdx.x; if (t < EE) { g_cnt[t] = 0; g_cur[t] = 0; } }

__global__ void gate_kernel(const float* __restrict__ Wg) {
    int gtid = blockIdx.x * blockDim.x + threadIdx.x;
    int warp = gtid >> 5, lane = gtid & 31;
    if (warp >= NN) return;
    const float* hp = g_h2 + (size_t)warp * DD;
    float best = -1e30f; int bi = 0;
    for (int e = 0; e < EE; e++) {
        float s = 0.f;
        for (int i = lane; i < DD; i += 32) s += hp[i] * Wg[i * EE + e];
#pragma unroll
        for (int o = 16; o; o >>= 1) s += __shfl_xor_sync(0xffffffffu, s, o);
        if (s > best) { best = s; bi = e; }
    }
    if (lane == 0) { g_sel[warp] = bi; atomicAdd(&g_cnt[bi], 1); }
}

__global__ void moe_scan() {
    if (threadIdx.x == 0) {
        int o = 0;
        for (int e = 0; e < EE; e++) { g_off[e] = o; o += ((g_cnt[e] + 127) >> 7) << 7; }
        g_off[EE] = o;
    }
}
__global__ void moe_scatter() {
    int n = blockIdx.x * 256 + threadIdx.x;
    if (n < NN) {
        int e = g_sel[n];
        int p = atomicAdd(&g_cur[e], 1);
        g_perm[g_off[e] + p] = n;
    }
}

// ---------------- expert FFN1 ---------------------------------------------------
__global__ __launch_bounds__(256, 2) void ffn1_tc(const float* __restrict__ W1,
                                                  const float* __restrict__ b1) {
    int row0 = blockIdx.x * 128;
    if (row0 >= g_off[EE]) return;
    int e = 0;
#pragma unroll
    for (int i = 1; i < EE; i++) if (row0 >= g_off[i]) e = i;
    int valid = g_cnt[e] - (row0 - g_off[e]);
    if (valid > 128) valid = 128;
    extern __shared__ float sm[];
    __shared__ int toks[128];
    int tid = threadIdx.x, lane = tid & 31, warp = tid >> 5;
    int g = lane >> 2, t = lane & 3;
    int mw = (warp >> 2) * 64, nw = (warp & 3) * 32;
    if (tid < 128) toks[tid] = (tid < valid) ? g_perm[row0 + tid] : g_perm[row0];
    __syncthreads();
    int n0 = blockIdx.y * 128;
    const float* wb = W1 + (size_t)e * DD * DFF;

    unsigned sbase = (unsigned)__cvta_generic_to_shared(sm);
    unsigned aLane = sbase + afrag_lane_off(lane, AS_STRIDE);
    const float* arow[4]; unsigned asmo[4];
    const float* brow[4]; unsigned bsmo[4];
#pragma unroll
    for (int i = 0; i < 4; i++) {
        int f = tid + i * 256;
        int r = f >> 3, kq = (f & 7) * 4;
        arow[i] = g_h2 + (size_t)toks[r] * DD + kq;
        asmo[i] = sbase + (r * AS_STRIDE + kq) * 4;
        int kk = f >> 5, nq = (f & 31) * 4;
        brow[i] = wb + (size_t)kk * DFF + n0 + nq;
        bsmo[i] = sbase + (B_BASE3 + kk * BS_STRIDE + nq) * 4;
    }
    float acc[4][4][4] = {};
    const int NC = DD / 32;
#pragma unroll
    for (int p = 0; p < 2; p++) {
        int k0 = p * 32;
#pragma unroll
        for (int i = 0; i < 4; i++) cpa16(asmo[i] + p * AS_BUF * 4, arow[i] + k0);
#pragma unroll
        for (int i = 0; i < 4; i++) cpa16(bsmo[i] + p * BS_BUF * 4, brow[i] + (size_t)k0 * DFF);
        cp_commit();
    }
#pragma unroll 1
    for (int c = 0; c < NC; c++) {
        if (c + 1 < NC) cp_wait1(); else cp_wait0();
        __syncthreads();
        int buf = c % 3;
        mma_chunk<true>(aLane + buf * AS_BUF * 4, sm + B_BASE3 + buf * BS_BUF, acc, g, t, mw, nw);
        if (c + 2 < NC) {
            int k0 = (c + 2) * 32, nb = (c + 2) % 3;
#pragma unroll
            for (int i = 0; i < 4; i++) cpa16(asmo[i] + nb * AS_BUF * 4, arow[i] + k0);
#pragma unroll
            for (int i = 0; i < 4; i++) cpa16(bsmo[i] + nb * BS_BUF * 4, brow[i] + (size_t)k0 * DFF);
            cp_commit();
        }
    }
#pragma unroll
    for (int mt = 0; mt < 4; mt++) {
#pragma unroll
        for (int nt = 0; nt < 4; nt++) {
            int col = n0 + nw + nt * 8 + 2 * t;
#pragma unroll
            for (int half = 0; half < 2; half++) {
                int lr = mw + mt * 16 + g + half * 8;
                if (lr < valid) {
                    float v0 = acc[mt][nt][half * 2]     + b1[(size_t)e * DFF + col];
                    float v1 = acc[mt][nt][half * 2 + 1] + b1[(size_t)e * DFF + col + 1];
                    float2 v = make_float2(tf32f(v0 > 0.f ? v0 : 0.f),
                                           tf32f(v1 > 0.f ? v1 : 0.f));
                    *(float2*)(g_hid + (size_t)(row0 + lr) * DFF + col) = v;
                }
            }
        }
    }
}

// ---------------- expert FFN2 ---------------------------------------------------
__global__ __launch_bounds__(256, 2) void ffn2_tc(const float* __restrict__ W2,
                                                  const float* __restrict__ b2,
                                                  float* __restrict__ out) {
    int row0 = blockIdx.x * 128;
    if (row0 >= g_off[EE]) return;
    int e = 0;
#pragma unroll
    for (int i = 1; i < EE; i++) if (row0 >= g_off[i]) e = i;
    int valid = g_cnt[e] - (row0 - g_off[e]);
    if (valid > 128) valid = 128;
    extern __shared__ float sm[];
    __shared__ int toks[128];
    int tid = threadIdx.x, lane = tid & 31, warp = tid >> 5;
    int g = lane >> 2, t = lane & 3;
    int mw = (warp >> 2) * 64, nw = (warp & 3) * 32;
    if (tid < 128) toks[tid] = (tid < valid) ? g_perm[row0 + tid] : 0;
    __syncthreads();
    int n0 = blockIdx.y * 128;
    const float* wb = W2 + (size_t)e * DFF * DD;

    unsigned sbase = (unsigned)__cvta_generic_to_shared(sm);
    unsigned aLane = sbase + afrag_lane_off(lane, AS_STRIDE);
    const float* arow[4]; unsigned asmo[4];
    const float* brow[4]; unsigned bsmo[4];
#pragma unroll
    for (int i = 0; i < 4; i++) {
        int f = tid + i * 256;
        int r = f >> 3, kq = (f & 7) * 4;
        arow[i] = g_hid + (size_t)(row0 + r) * DFF + kq;
        asmo[i] = sbase + (r * AS_STRIDE + kq) * 4;
        int kk = f >> 5, nq = (f & 31) * 4;
        brow[i] = wb + (size_t)kk * DD + n0 + nq;
        bsmo[i] = sbase + (B_BASE3 + kk * BS_STRIDE + nq) * 4;
    }
    float acc[4][4][4] = {};
    const int NC = DFF / 32;   // 96
#pragma unroll
    for (int p = 0; p < 2; p++) {
        int k0 = p * 32;
#pragma unroll
        for (int i = 0; i < 4; i++) cpa16(asmo[i] + p * AS_BUF * 4, arow[i] + k0);
#pragma unroll
        for (int i = 0; i < 4; i++) cpa16(bsmo[i] + p * BS_BUF * 4, brow[i] + (size_t)k0 * DD);
        cp_commit();
    }
#pragma unroll 1
    for (int c = 0; c < NC; c++) {
        if (c + 1 < NC) cp_wait1(); else cp_wait0();
        __syncthreads();
        int buf = c % 3;
        mma_chunk<false>(aLane + buf * AS_BUF * 4, sm + B_BASE3 + buf * BS_BUF, acc, g, t, mw, nw);
        if (c + 2 < NC) {
            int k0 = (c + 2) * 32, nb = (c + 2) % 3;
#pragma unroll
            for (int i = 0; i < 4; i++) cpa16(asmo[i] + nb * AS_BUF * 4, arow[i] + k0);
#pragma unroll
            for (int i = 0; i < 4; i++) cpa16(bsmo[i] + nb * BS_BUF * 4, brow[i] + (size_t)k0 * DD);
            cp_commit();
        }
    }
#pragma unroll
    for (int mt = 0; mt < 4; mt++) {
#pragma unroll
        for (int nt = 0; nt < 4; nt++) {
            int col = n0 + nw + nt * 8 + 2 * t;
#pragma unroll
            for (int half = 0; half < 2; half++) {
                int lr = mw + mt * 16 + g + half * 8;
                if (lr < valid) {
                    int tok = toks[lr];
                    size_t idx = (size_t)tok * DD + col;
                    out[idx]     += acc[mt][nt][half * 2]     + b2[(size_t)e * DD + col];
                    out[idx + 1] += acc[mt][nt][half * 2 + 1] + b2[(size_t)e * DD + col + 1];
                }
            }
        }
    }
}

// ---------------- launch -------------------------------------------------------
extern "C" void kernel_launch(void* const* d_in, const int* in_sizes, int n_in,
                              void* d_out, int out_size) {
    const float* x     = (const float*)d_in[0];
    const float* ln1_g = (const float*)d_in[1];
    const float* ln1_b = (const float*)d_in[2];
    const float* ln2_g = (const float*)d_in[3];
    const float* ln2_b = (const float*)d_in[4];
    const float* Wq    = (const float*)d_in[5];
    const float* Wk    = (const float*)d_in[6];
    const float* Wv    = (const float*)d_in[7];
    const float* Wp    = (const float*)d_in[8];
    const float* bp    = (const float*)d_in[9];
    const float* Wg    = (const float*)d_in[10];
    const float* W1    = (const float*)d_in[11];
    const float* b1    = (const float*)d_in[12];
    const float* W2    = (const float*)d_in[13];
    const float* b2    = (const float*)d_in[14];
    float* out = (float*)d_out;

    const int smem_g = SMEM_G_FLOATS * 4;        // 107520
    const int smem_a = ATT_SMEM_FLOATS * 4;      // 141312
    static bool attr_set = false;
    if (!attr_set) {
        cudaFuncSetAttribute(qkv_tc,  cudaFuncAttributeMaxDynamicSharedMemorySize, smem_g);
        cudaFuncSetAttribute(proj_tc, cudaFuncAttributeMaxDynamicSharedMemorySize, smem_g);
        cudaFuncSetAttribute(ffn1_tc, cudaFuncAttributeMaxDynamicSharedMemorySize, smem_g);
        cudaFuncSetAttribute(ffn2_tc, cudaFuncAttributeMaxDynamicSharedMemorySize, smem_g);
        cudaFuncSetAttribute(attn_tc, cudaFuncAttributeMaxDynamicSharedMemorySize, smem_a);
        attr_set = true;
    }

    ln_kernel<<<NN, 256>>>(x, ln1_g, ln1_b, 0);
    qkv_tc<<<dim3(NN / 128, 18), 256, smem_g>>>(Wq, Wk, Wv);
    attn_tc<<<dim3(TT / 128, HH, BB), 256, smem_a>>>();
    proj_tc<<<dim3(NN / 128, DD / 128), 256, smem_g>>>(Wp, bp, x, out);
    ln_kernel<<<NN, 256>>>(out, ln2_g, ln2_b, 1);
    moe_zero<<<1, 32>>>();
    gate_kernel<<<NN * 32 / 256, 256>>>(Wg);
    moe_scan<<<1, 1>>>();
    moe_scatter<<<NN / 256, 256>>>();
    ffn1_tc<<<dim3(NPAD / 128, DFF / 128), 256, smem_g>>>(W1, b1);
    ffn2_tc<<<dim3(NPAD / 128, DD / 128), 256, smem_g>>>(W2, b2, out);
}

// round 15
// speedup vs baseline: 3.9022x; 1.0467x over previous
#include <cuda_runtime.h>
#include <cstdint>

// Problem dims
#define BB 2
#define TT 1024
#define DD 768
#define HH 12
#define HSZ 64
#define EE 8
#define DFF 3072
#define NN 2048
#define NPAD 3072

// GEMM tiling: block 128x64, warp 32x32, 3-stage pipeline
#define AS_STRIDE 36                  // 36j mod 32 = 4j -> LDSM rows conflict-free
#define BS_STRIDE 72                  // 72 mod 32 = 8 -> bank 8t+g distinct
#define AS_BUF (128 * AS_STRIDE)      // 4608 floats
#define BS_BUF (32 * BS_STRIDE)       // 2304 floats
#define B_BASE3 (3 * AS_BUF)
#define SMEM_G_FLOATS (3 * (AS_BUF + BS_BUF))   // 20736 floats = 82944 B

// Attention smem layout (floats)
#define QS_STR 68
#define KS_STR 68
#define VS_STR 72
#define PS_STR 68
#define AQ 0
#define AK (128 * QS_STR)
#define AV (AK + 2 * 64 * KS_STR)
#define AP (AV + 2 * 64 * VS_STR)
#define ATT_SMEM_FLOATS (AP + 128 * PS_STR)     // 35328 floats = 141312 B

// ---------------- scratch ------------------------------------------------------
__device__ float g_h[NN * DD];
__device__ float g_q[NN * DD];
__device__ float g_k[NN * DD];
__device__ float g_v[NN * DD];
__device__ float g_att[NN * DD];
__device__ float g_h2[NN * DD];
__device__ float g_hid[NPAD * DFF];
__device__ int   g_sel[NN];
__device__ int   g_cnt[EE];
__device__ int   g_cur[EE];
__device__ int   g_off[EE + 1];
__device__ int   g_perm[NPAD];

// ---------------- helpers ------------------------------------------------------
__device__ __forceinline__ void cpa16(unsigned s, const float* g) {
    asm volatile("cp.async.ca.shared.global [%0], [%1], 16;\n" :: "r"(s), "l"(g));
}
__device__ __forceinline__ void cp_commit() { asm volatile("cp.async.commit_group;\n"); }
__device__ __forceinline__ void cp_wait1() { asm volatile("cp.async.wait_group 1;\n"); }
__device__ __forceinline__ void cp_wait0() { asm volatile("cp.async.wait_group 0;\n"); }

__device__ __forceinline__ unsigned cvt_tf32(float v) {
    unsigned r;
    asm("cvt.rna.tf32.f32 %0, %1;" : "=r"(r) : "f"(v));
    return r;
}
__device__ __forceinline__ float tf32f(float v) { return __uint_as_float(cvt_tf32(v)); }

__device__ __forceinline__ void ldsm4(unsigned& r0, unsigned& r1, unsigned& r2, unsigned& r3,
                                      unsigned addr) {
    asm volatile("ldmatrix.sync.aligned.m8n8.x4.shared.b16 {%0,%1,%2,%3}, [%4];"
        : "=r"(r0), "=r"(r1), "=r"(r2), "=r"(r3) : "r"(addr));
}

__device__ __forceinline__ void mma8(float* c, const unsigned* a, const unsigned* b) {
    asm volatile(
        "mma.sync.aligned.m16n8k8.row.col.f32.tf32.tf32.f32 "
        "{%0,%1,%2,%3},{%4,%5,%6,%7},{%8,%9},{%0,%1,%2,%3};\n"
        : "+f"(c[0]), "+f"(c[1]), "+f"(c[2]), "+f"(c[3])
        : "r"(a[0]), "r"(a[1]), "r"(a[2]), "r"(a[3]), "r"(b[0]), "r"(b[1]));
}

// A-fragment lane address offset for LDSM x4
__device__ __forceinline__ unsigned afrag_lane_off(int lane, int stride_f) {
    int row_l = (lane & 7) + ((lane >> 3) & 1) * 8;
    int col_l = (lane >> 4) * 4;
    return (unsigned)((row_l * stride_f + col_l) * 4);
}
// B-fragment (row-major [n][k] smem) lane offset
__device__ __forceinline__ unsigned bfrag_lane_off(int lane, int stride_f) {
    int row_l = (lane & 7) + (lane >> 4) * 8;
    int col_l = ((lane >> 3) & 1) * 4;
    return (unsigned)((row_l * stride_f + col_l) * 4);
}

// one 32-wide K chunk: warp tile 32x32 (2 mt x 4 nt). A via LDSM (optional rna),
// B (weights, [k][n] smem) scalar + rna cvt.
template<bool CVTA>
__device__ __forceinline__ void mma_chunk(unsigned aAddr, const float* __restrict__ sB,
                                          float acc[2][4][4], int g, int t, int mw, int nw) {
#pragma unroll
    for (int ks = 0; ks < 4; ks++) {
        int k8 = ks * 8;
        unsigned a[2][4], b[4][2];
#pragma unroll
        for (int mt = 0; mt < 2; mt++) {
            unsigned ad = aAddr + (unsigned)(((mw + mt * 16) * AS_STRIDE + k8) * 4);
            ldsm4(a[mt][0], a[mt][1], a[mt][2], a[mt][3], ad);
            if (CVTA) {
                a[mt][0] = cvt_tf32(__uint_as_float(a[mt][0]));
                a[mt][1] = cvt_tf32(__uint_as_float(a[mt][1]));
                a[mt][2] = cvt_tf32(__uint_as_float(a[mt][2]));
                a[mt][3] = cvt_tf32(__uint_as_float(a[mt][3]));
            }
        }
#pragma unroll
        for (int nt = 0; nt < 4; nt++) {
            int cn = nw + nt * 8 + g;
            b[nt][0] = cvt_tf32(sB[(k8 + t) * BS_STRIDE + cn]);
            b[nt][1] = cvt_tf32(sB[(k8 + t + 4) * BS_STRIDE + cn]);
        }
#pragma unroll
        for (int mt = 0; mt < 2; mt++)
#pragma unroll
            for (int nt = 0; nt < 4; nt++)
                mma8(acc[mt][nt], a[mt], b[nt]);
    }
}

// ---------------- LayerNorm ----------------------------------------------------
__global__ void ln_kernel(const float* __restrict__ x, const float* __restrict__ gw,
                          const float* __restrict__ gb, int which) {
    float* out = which ? g_h2 : g_h;
    int row = blockIdx.x, tid = threadIdx.x;
    const float* xp = x + (size_t)row * DD;
    float v0 = xp[tid], v1 = xp[tid + 256], v2 = xp[tid + 512];
    float s = v0 + v1 + v2;
    float s2 = v0 * v0 + v1 * v1 + v2 * v2;
#pragma unroll
    for (int o = 16; o; o >>= 1) {
        s  += __shfl_xor_sync(0xffffffffu, s, o);
        s2 += __shfl_xor_sync(0xffffffffu, s2, o);
    }
    __shared__ float r1[8], r2[8];
    if ((tid & 31) == 0) { r1[tid >> 5] = s; r2[tid >> 5] = s2; }
    __syncthreads();
    s = 0.f; s2 = 0.f;
#pragma unroll
    for (int i = 0; i < 8; i++) { s += r1[i]; s2 += r2[i]; }
    float mu = s * (1.f / DD);
    float var = s2 * (1.f / DD) - mu * mu;
    float rs = rsqrtf(var + 1e-5f);
    float* op = out + (size_t)row * DD;
    float o0 = (v0 - mu) * rs * gw[tid]       + gb[tid];
    float o1 = (v1 - mu) * rs * gw[tid + 256] + gb[tid + 256];
    float o2 = (v2 - mu) * rs * gw[tid + 512] + gb[tid + 512];
    if (which == 0) { o0 = tf32f(o0); o1 = tf32f(o1); o2 = tf32f(o2); }
    op[tid] = o0; op[tid + 256] = o1; op[tid + 512] = o2;
}

// ---------------- QKV gemm -----------------------------------------------------
// grid (16, 36): y/12 -> matrix, y%12 -> 64-wide ntile (= one head).
__global__ __launch_bounds__(256, 2) void qkv_tc(
    const float* __restrict__ Wq, const float* __restrict__ Wk, const float* __restrict__ Wv) {
    extern __shared__ float sm[];
    int tid = threadIdx.x, lane = tid & 31, warp = tid >> 5;
    int g = lane >> 2, t = lane & 3;
    int mw = (warp >> 1) * 32, nw = (warp & 1) * 32;
    int m0 = blockIdx.x * 128;
    int y = blockIdx.y;
    int mat = y / 12, h = y % 12;
    const float* W = (mat == 0) ? Wq : (mat == 1 ? Wk : Wv);
    float* dst = (mat == 0) ? g_q : (mat == 1 ? g_k : g_v);
    const float* wb = W + (size_t)h * DD * HSZ;

    unsigned sbase = (unsigned)__cvta_generic_to_shared(sm);
    unsigned aLane = sbase + afrag_lane_off(lane, AS_STRIDE);
    const float* arow[4]; unsigned asmo[4];
    const float* brow[2]; unsigned bsmo[2];
#pragma unroll
    for (int i = 0; i < 4; i++) {
        int f = tid + i * 256;
        int r = f >> 3, kq = (f & 7) * 4;
        arow[i] = g_h + (size_t)(m0 + r) * DD + kq;
        asmo[i] = sbase + (r * AS_STRIDE + kq) * 4;
    }
#pragma unroll
    for (int i = 0; i < 2; i++) {
        int f = tid + i * 256;
        int kk = f >> 4, nq = (f & 15) * 4;
        brow[i] = wb + (size_t)kk * HSZ + nq;
        bsmo[i] = sbase + (B_BASE3 + kk * BS_STRIDE + nq) * 4;
    }
    float acc[2][4][4] = {};
    const int NC = DD / 32;  // 24
#pragma unroll
    for (int p = 0; p < 2; p++) {
        int k0 = p * 32;
#pragma unroll
        for (int i = 0; i < 4; i++) cpa16(asmo[i] + p * AS_BUF * 4, arow[i] + k0);
#pragma unroll
        for (int i = 0; i < 2; i++) cpa16(bsmo[i] + p * BS_BUF * 4, brow[i] + k0 * HSZ);
        cp_commit();
    }
#pragma unroll 1
    for (int c = 0; c < NC; c++) {
        if (c + 1 < NC) cp_wait1(); else cp_wait0();
        __syncthreads();
        int buf = c % 3;
        mma_chunk<false>(aLane + buf * AS_BUF * 4, sm + B_BASE3 + buf * BS_BUF, acc, g, t, mw, nw);
        if (c + 2 < NC) {
            int k0 = (c + 2) * 32, nb = (c + 2) % 3;
#pragma unroll
            for (int i = 0; i < 4; i++) cpa16(asmo[i] + nb * AS_BUF * 4, arow[i] + k0);
#pragma unroll
            for (int i = 0; i < 2; i++) cpa16(bsmo[i] + nb * BS_BUF * 4, brow[i] + k0 * HSZ);
            cp_commit();
        }
    }
#pragma unroll
    for (int mt = 0; mt < 2; mt++) {
#pragma unroll
        for (int nt = 0; nt < 4; nt++) {
            int col = nw + nt * 8 + 2 * t;     // 0..63 within head
#pragma unroll
            for (int half = 0; half < 2; half++) {
                int m = m0 + mw + mt * 16 + g + half * 8;
                int b_ = m >> 10, t_ = m & 1023;
                float2 v = make_float2(tf32f(acc[mt][nt][half * 2]),
                                       tf32f(acc[mt][nt][half * 2 + 1]));
                *(float2*)(dst + (((size_t)(b_ * HH + h) * TT + t_) << 6) + col) = v;
            }
        }
    }
}

// ---------------- tensor-core flash attention ---------------------------------
__global__ __launch_bounds__(256) void attn_tc() {
    extern __shared__ float sm[];
    int tid = threadIdx.x, lane = tid & 31, w = tid >> 5;
    int g = lane >> 2, t = lane & 3;
    int qt = (int)gridDim.x - 1 - (int)blockIdx.x;
    int h = blockIdx.y, b = blockIdx.z;
    int m0 = qt * 128;
    const float scale = rsqrtf((float)DD);
    const float* qbase = g_q + ((size_t)(b * HH + h) * TT + m0) * HSZ;
    const float* kbase = g_k + (size_t)(b * HH + h) * TT * HSZ;
    const float* vbase = g_v + (size_t)(b * HH + h) * TT * HSZ;
    unsigned sbase = (unsigned)__cvta_generic_to_shared(sm);
    unsigned qLane = sbase + AQ * 4 + afrag_lane_off(lane, QS_STR);
    unsigned pLane = sbase + AP * 4 + afrag_lane_off(lane, PS_STR);
    unsigned kLane = sbase + AK * 4 + bfrag_lane_off(lane, KS_STR);

    int ntiles = 2 * (qt + 1);
    int r_ = tid >> 4, c_ = (tid & 15) * 4;
    {
#pragma unroll
        for (int i = 0; i < 4; i++) {
            int rr = r_ + i * 16;
            cpa16(sbase + (AK + rr * KS_STR + c_) * 4, kbase + rr * HSZ + c_);
            cpa16(sbase + (AV + rr * VS_STR + c_) * 4, vbase + rr * HSZ + c_);
        }
        cp_commit();
    }
#pragma unroll
    for (int i = 0; i < 8; i++) {
        int f = tid + i * 256;
        int rr = f >> 4, cc = (f & 15) * 4;
        float4 v = *(const float4*)(qbase + (size_t)rr * HSZ + cc);
        v.x = tf32f(v.x * scale); v.y = tf32f(v.y * scale);
        v.z = tf32f(v.z * scale); v.w = tf32f(v.w * scale);
        *(float4*)&sm[AQ + rr * QS_STR + cc] = v;
    }

    int mw = w * 16;
    int qrow0 = m0 + mw + g, qrow1 = qrow0 + 8;
    float m0s = -1e30f, m1s = -1e30f, l0s = 0.f, l1s = 0.f;
    float acc_o[8][4] = {};

#pragma unroll 1
    for (int kt = 0; kt < ntiles; kt++) {
        cp_wait0();
        __syncthreads();
        int buf = kt & 1;
        if (kt + 1 < ntiles) {
            const float* kp = kbase + (size_t)(kt + 1) * 64 * HSZ;
            const float* vp = vbase + (size_t)(kt + 1) * 64 * HSZ;
            int ob = buf ^ 1;
#pragma unroll
            for (int i = 0; i < 4; i++) {
                int rr = r_ + i * 16;
                cpa16(sbase + (AK + ob * 64 * KS_STR + rr * KS_STR + c_) * 4, kp + rr * HSZ + c_);
                cpa16(sbase + (AV + ob * 64 * VS_STR + rr * VS_STR + c_) * 4, vp + rr * HSZ + c_);
            }
            cp_commit();
        }
        const float* vs_ = sm + AV + buf * 64 * VS_STR;
        unsigned kBufLane = kLane + (unsigned)(buf * 64 * KS_STR * 4);

        float s_acc[8][4];
#pragma unroll
        for (int nt = 0; nt < 8; nt++) { s_acc[nt][0] = s_acc[nt][1] = s_acc[nt][2] = s_acc[nt][3] = 0.f; }
#pragma unroll
        for (int k8i = 0; k8i < 8; k8i++) {
            int k8 = k8i * 8;
            unsigned a[4];
            ldsm4(a[0], a[1], a[2], a[3], qLane + (unsigned)((mw * QS_STR + k8) * 4));
#pragma unroll
            for (int p = 0; p < 4; p++) {
                unsigned b0, b1, b2, b3;
                ldsm4(b0, b1, b2, b3, kBufLane + (unsigned)((p * 16 * KS_STR + k8) * 4));
                unsigned bb0[2] = {b0, b1}, bb1[2] = {b2, b3};
                mma8(s_acc[2 * p], a, bb0);
                mma8(s_acc[2 * p + 1], a, bb1);
            }
        }
        int k0 = kt * 64;
        if (kt >= 2 * qt) {
#pragma unroll
            for (int nt = 0; nt < 8; nt++) {
                int c0 = k0 + nt * 8 + 2 * t, c1 = c0 + 1;
                if (c0 > qrow0) s_acc[nt][0] = -1e30f;
                if (c1 > qrow0) s_acc[nt][1] = -1e30f;
                if (c0 > qrow1) s_acc[nt][2] = -1e30f;
                if (c1 > qrow1) s_acc[nt][3] = -1e30f;
            }
        }
        float mt0 = m0s, mt1 = m1s;
#pragma unroll
        for (int nt = 0; nt < 8; nt++) {
            mt0 = fmaxf(mt0, fmaxf(s_acc[nt][0], s_acc[nt][1]));
            mt1 = fmaxf(mt1, fmaxf(s_acc[nt][2], s_acc[nt][3]));
        }
        mt0 = fmaxf(mt0, __shfl_xor_sync(0xffffffffu, mt0, 1));
        mt0 = fmaxf(mt0, __shfl_xor_sync(0xffffffffu, mt0, 2));
        mt1 = fmaxf(mt1, __shfl_xor_sync(0xffffffffu, mt1, 1));
        mt1 = fmaxf(mt1, __shfl_xor_sync(0xffffffffu, mt1, 2));
        float r0 = __expf(m0s - mt0), r1 = __expf(m1s - mt1);
        m0s = mt0; m1s = mt1;
        float ls0 = 0.f, ls1 = 0.f;
#pragma unroll
        for (int nt = 0; nt < 8; nt++) {
            float p0 = __expf(s_acc[nt][0] - mt0);
            float p1 = __expf(s_acc[nt][1] - mt0);
            float p2 = __expf(s_acc[nt][2] - mt1);
            float p3 = __expf(s_acc[nt][3] - mt1);
            ls0 += p0 + p1; ls1 += p2 + p3;
            int cc = nt * 8 + 2 * t;
            *(float2*)&sm[AP + (mw + g) * PS_STR + cc]     = make_float2(tf32f(p0), tf32f(p1));
            *(float2*)&sm[AP + (mw + g + 8) * PS_STR + cc] = make_float2(tf32f(p2), tf32f(p3));
        }
        ls0 += __shfl_xor_sync(0xffffffffu, ls0, 1);
        ls0 += __shfl_xor_sync(0xffffffffu, ls0, 2);
        ls1 += __shfl_xor_sync(0xffffffffu, ls1, 1);
        ls1 += __shfl_xor_sync(0xffffffffu, ls1, 2);
        l0s = l0s * r0 + ls0;
        l1s = l1s * r1 + ls1;
#pragma unroll
        for (int nt = 0; nt < 8; nt++) {
            acc_o[nt][0] *= r0; acc_o[nt][1] *= r0;
            acc_o[nt][2] *= r1; acc_o[nt][3] *= r1;
        }
        __syncwarp();

#pragma unroll
        for (int k8i = 0; k8i < 8; k8i++) {
            int k8 = k8i * 8;
            unsigned a[4];
            ldsm4(a[0], a[1], a[2], a[3], pLane + (unsigned)((mw * PS_STR + k8) * 4));
#pragma unroll
            for (int nt = 0; nt < 8; nt++) {
                unsigned bf[2];
                bf[0] = __float_as_uint(vs_[(k8 + t) * VS_STR + nt * 8 + g]);
                bf[1] = __float_as_uint(vs_[(k8 + t + 4) * VS_STR + nt * 8 + g]);
                mma8(acc_o[nt], a, bf);
            }
        }
        __syncwarp();
    }
    float inv0 = 1.f / l0s, inv1 = 1.f / l1s;
    float* o0 = g_att + ((size_t)(b * TT) + qrow0) * DD + h * HSZ;
    float* o1 = g_att + ((size_t)(b * TT) + qrow1) * DD + h * HSZ;
#pragma unroll
    for (int nt = 0; nt < 8; nt++) {
        int cc = nt * 8 + 2 * t;
        *(float2*)(o0 + cc) = make_float2(tf32f(acc_o[nt][0] * inv0), tf32f(acc_o[nt][1] * inv0));
        *(float2*)(o1 + cc) = make_float2(tf32f(acc_o[nt][2] * inv1), tf32f(acc_o[nt][3] * inv1));
    }
}

// ---------------- output projection + residual ---------------------------------
// grid (16, 12)
__global__ __launch_bounds__(256, 2) void proj_tc(
    const float* __restrict__ Wp, const float* __restrict__ bp,
    const float* __restrict__ x, float* __restrict__ out) {
    extern __shared__ float sm[];
    int tid = threadIdx.x, lane = tid & 31, warp = tid >> 5;
    int g = lane >> 2, t = lane & 3;
    int mw = (warp >> 1) * 32, nw = (warp & 1) * 32;
    int m0 = blockIdx.x * 128;
    int n0 = blockIdx.y * 64;

    unsigned sbase = (unsigned)__cvta_generic_to_shared(sm);
    unsigned aLane = sbase + afrag_lane_off(lane, AS_STRIDE);
    const float* arow[4]; unsigned asmo[4];
    const float* brow[2]; unsigned bsmo[2];
#pragma unroll
    for (int i = 0; i < 4; i++) {
        int f = tid + i * 256;
        int r = f >> 3, kq = (f & 7) * 4;
        arow[i] = g_att + (size_t)(m0 + r) * DD + kq;
        asmo[i] = sbase + (r * AS_STRIDE + kq) * 4;
    }
#pragma unroll
    for (int i = 0; i < 2; i++) {
        int f = tid + i * 256;
        int kk = f >> 4, nq = (f & 15) * 4;
        brow[i] = Wp + (size_t)kk * DD + n0 + nq;
        bsmo[i] = sbase + (B_BASE3 + kk * BS_STRIDE + nq) * 4;
    }
    float acc[2][4][4] = {};
    const int NC = DD / 32;
#pragma unroll
    for (int p = 0; p < 2; p++) {
        int k0 = p * 32;
#pragma unroll
        for (int i = 0; i < 4; i++) cpa16(asmo[i] + p * AS_BUF * 4, arow[i] + k0);
#pragma unroll
        for (int i = 0; i < 2; i++) cpa16(bsmo[i] + p * BS_BUF * 4, brow[i] + (size_t)k0 * DD);
        cp_commit();
    }
#pragma unroll 1
    for (int c = 0; c < NC; c++) {
        if (c + 1 < NC) cp_wait1(); else cp_wait0();
        __syncthreads();
        int buf = c % 3;
        mma_chunk<false>(aLane + buf * AS_BUF * 4, sm + B_BASE3 + buf * BS_BUF, acc, g, t, mw, nw);
        if (c + 2 < NC) {
            int k0 = (c + 2) * 32, nb = (c + 2) % 3;
#pragma unroll
            for (int i = 0; i < 4; i++) cpa16(asmo[i] + nb * AS_BUF * 4, arow[i] + k0);
#pragma unroll
            for (int i = 0; i < 2; i++) cpa16(bsmo[i] + nb * BS_BUF * 4, brow[i] + (size_t)k0 * DD);
            cp_commit();
        }
    }
#pragma unroll
    for (int mt = 0; mt < 2; mt++) {
#pragma unroll
        for (int nt = 0; nt < 4; nt++) {
            int col = n0 + nw + nt * 8 + 2 * t;
#pragma unroll
            for (int half = 0; half < 2; half++) {
                int m = m0 + mw + mt * 16 + g + half * 8;
                size_t idx = (size_t)m * DD + col;
                out[idx]     = acc[mt][nt][half * 2]     + bp[col]     + x[idx];
                out[idx + 1] = acc[mt][nt][half * 2 + 1] + bp[col + 1] + x[idx + 1];
            }
        }
    }
}

// ---------------- MoE gate + routing -------------------------------------------
__global__ void moe_zero() { int t = threadIdx.x; if (t < EE) { g_cnt[t] = 0; g_cur[t] = 0; } }

__global__ void gate_kernel(const float* __restrict__ Wg) {
    int gtid = blockIdx.x * blockDim.x + threadIdx.x;
    int warp = gtid >> 5, lane = gtid & 31;
    if (warp >= NN) return;
    const float* hp = g_h2 + (size_t)warp * DD;
    float best = -1e30f; int bi = 0;
    for (int e = 0; e < EE; e++) {
        float s = 0.f;
        for (int i = lane; i < DD; i += 32) s += hp[i] * Wg[i * EE + e];
#pragma unroll
        for (int o = 16; o; o >>= 1) s += __shfl_xor_sync(0xffffffffu, s, o);
        if (s > best) { best = s; bi = e; }
    }
    if (lane == 0) { g_sel[warp] = bi; atomicAdd(&g_cnt[bi], 1); }
}

__global__ void moe_scan() {
    if (threadIdx.x == 0) {
        int o = 0;
        for (int e = 0; e < EE; e++) { g_off[e] = o; o += ((g_cnt[e] + 127) >> 7) << 7; }
        g_off[EE] = o;
    }
}
__global__ void moe_scatter() {
    int n = blockIdx.x * 256 + threadIdx.x;
    if (n < NN) {
        int e = g_sel[n];
        int p = atomicAdd(&g_cur[e], 1);
        g_perm[g_off[e] + p] = n;
    }
}

// ---------------- expert FFN1 ---------------------------------------------------
// grid (24, 48)
__global__ __launch_bounds__(256, 2) void ffn1_tc(const float* __restrict__ W1,
                                                  const float* __restrict__ b1) {
    int row0 = blockIdx.x * 128;
    if (row0 >= g_off[EE]) return;
    int e = 0;
#pragma unroll
    for (int i = 1; i < EE; i++) if (row0 >= g_off[i]) e = i;
    int valid = g_cnt[e] - (row0 - g_off[e]);
    if (valid > 128) valid = 128;
    extern __shared__ float sm[];
    __shared__ int toks[128];
    int tid = threadIdx.x, lane = tid & 31, warp = tid >> 5;
    int g = lane >> 2, t = lane & 3;
    int mw = (warp >> 1) * 32, nw = (warp & 1) * 32;
    if (tid < 128) toks[tid] = (tid < valid) ? g_perm[row0 + tid] : g_perm[row0];
    __syncthreads();
    int n0 = blockIdx.y * 64;
    const float* wb = W1 + (size_t)e * DD * DFF;

    unsigned sbase = (unsigned)__cvta_generic_to_shared(sm);
    unsigned aLane = sbase + afrag_lane_off(lane, AS_STRIDE);
    const float* arow[4]; unsigned asmo[4];
    const float* brow[2]; unsigned bsmo[2];
#pragma unroll
    for (int i = 0; i < 4; i++) {
        int f = tid + i * 256;
        int r = f >> 3, kq = (f & 7) * 4;
        arow[i] = g_h2 + (size_t)toks[r] * DD + kq;
        asmo[i] = sbase + (r * AS_STRIDE + kq) * 4;
    }
#pragma unroll
    for (int i = 0; i < 2; i++) {
        int f = tid + i * 256;
        int kk = f >> 4, nq = (f & 15) * 4;
        brow[i] = wb + (size_t)kk * DFF + n0 + nq;
        bsmo[i] = sbase + (B_BASE3 + kk * BS_STRIDE + nq) * 4;
    }
    float acc[2][4][4] = {};
    const int NC = DD / 32;
#pragma unroll
    for (int p = 0; p < 2; p++) {
        int k0 = p * 32;
#pragma unroll
        for (int i = 0; i < 4; i++) cpa16(asmo[i] + p * AS_BUF * 4, arow[i] + k0);
#pragma unroll
        for (int i = 0; i < 2; i++) cpa16(bsmo[i] + p * BS_BUF * 4, brow[i] + (size_t)k0 * DFF);
        cp_commit();
    }
#pragma unroll 1
    for (int c = 0; c < NC; c++) {
        if (c + 1 < NC) cp_wait1(); else cp_wait0();
        __syncthreads();
        int buf = c % 3;
        mma_chunk<true>(aLane + buf * AS_BUF * 4, sm + B_BASE3 + buf * BS_BUF, acc, g, t, mw, nw);
        if (c + 2 < NC) {
            int k0 = (c + 2) * 32, nb = (c + 2) % 3;
#pragma unroll
            for (int i = 0; i < 4; i++) cpa16(asmo[i] + nb * AS_BUF * 4, arow[i] + k0);
#pragma unroll
            for (int i = 0; i < 2; i++) cpa16(bsmo[i] + nb * BS_BUF * 4, brow[i] + (size_t)k0 * DFF);
            cp_commit();
        }
    }
#pragma unroll
    for (int mt = 0; mt < 2; mt++) {
#pragma unroll
        for (int nt = 0; nt < 4; nt++) {
            int col = n0 + nw + nt * 8 + 2 * t;
#pragma unroll
            for (int half = 0; half < 2; half++) {
                int lr = mw + mt * 16 + g + half * 8;
                if (lr < valid) {
                    float v0 = acc[mt][nt][half * 2]     + b1[(size_t)e * DFF + col];
                    float v1 = acc[mt][nt][half * 2 + 1] + b1[(size_t)e * DFF + col + 1];
                    float2 v = make_float2(tf32f(v0 > 0.f ? v0 : 0.f),
                                           tf32f(v1 > 0.f ? v1 : 0.f));
                    *(float2*)(g_hid + (size_t)(row0 + lr) * DFF + col) = v;
                }
            }
        }
    }
}

// ---------------- expert FFN2 ---------------------------------------------------
// grid (24, 12), K = 3072
__global__ __launch_bounds__(256, 2) void ffn2_tc(const float* __restrict__ W2,
                                                  const float* __restrict__ b2,
                                                  float* __restrict__ out) {
    int row0 = blockIdx.x * 128;
    if (row0 >= g_off[EE]) return;
    int e = 0;
#pragma unroll
    for (int i = 1; i < EE; i++) if (row0 >= g_off[i]) e = i;
    int valid = g_cnt[e] - (row0 - g_off[e]);
    if (valid > 128) valid = 128;
    extern __shared__ float sm[];
    __shared__ int toks[128];
    int tid = threadIdx.x, lane = tid & 31, warp = tid >> 5;
    int g = lane >> 2, t = lane & 3;
    int mw = (warp >> 1) * 32, nw = (warp & 1) * 32;
    if (tid < 128) toks[tid] = (tid < valid) ? g_perm[row0 + tid] : 0;
    __syncthreads();
    int n0 = blockIdx.y * 64;
    const float* wb = W2 + (size_t)e * DFF * DD;

    unsigned sbase = (unsigned)__cvta_generic_to_shared(sm);
    unsigned aLane = sbase + afrag_lane_off(lane, AS_STRIDE);
    const float* arow[4]; unsigned asmo[4];
    const float* brow[2]; unsigned bsmo[2];
#pragma unroll
    for (int i = 0; i < 4; i++) {
        int f = tid + i * 256;
        int r = f >> 3, kq = (f & 7) * 4;
        arow[i] = g_hid + (size_t)(row0 + r) * DFF + kq;
        asmo[i] = sbase + (r * AS_STRIDE + kq) * 4;
    }
#pragma unroll
    for (int i = 0; i < 2; i++) {
        int f = tid + i * 256;
        int kk = f >> 4, nq = (f & 15) * 4;
        brow[i] = wb + (size_t)kk * DD + n0 + nq;
        bsmo[i] = sbase + (B_BASE3 + kk * BS_STRIDE + nq) * 4;
    }
    float acc[2][4][4] = {};
    const int NC = DFF / 32;   // 96
#pragma unroll
    for (int p = 0; p < 2; p++) {
        int k0 = p * 32;
#pragma unroll
        for (int i = 0; i < 4; i++) cpa16(asmo[i] + p * AS_BUF * 4, arow[i] + k0);
#pragma unroll
        for (int i = 0; i < 2; i++) cpa16(bsmo[i] + p * BS_BUF * 4, brow[i] + (size_t)k0 * DD);
        cp_commit();
    }
#pragma unroll 1
    for (int c = 0; c < NC; c++) {
        if (c + 1 < NC) cp_wait1(); else cp_wait0();
        __syncthreads();
        int buf = c % 3;
        mma_chunk<false>(aLane + buf * AS_BUF * 4, sm + B_BASE3 + buf * BS_BUF, acc, g, t, mw, nw);
        if (c + 2 < NC) {
            int k0 = (c + 2) * 32, nb = (c + 2) % 3;
#pragma unroll
            for (int i = 0; i < 4; i++) cpa16(asmo[i] + nb * AS_BUF * 4, arow[i] + k0);
#pragma unroll
            for (int i = 0; i < 2; i++) cpa16(bsmo[i] + nb * BS_BUF * 4, brow[i] + (size_t)k0 * DD);
            cp_commit();
        }
    }
#pragma unroll
    for (int mt = 0; mt < 2; mt++) {
#pragma unroll
        for (int nt = 0; nt < 4; nt++) {
            int col = n0 + nw + nt * 8 + 2 * t;
#pragma unroll
            for (int half = 0; half < 2; half++) {
                int lr = mw + mt * 16 + g + half * 8;
                if (lr < valid) {
                    int tok = toks[lr];
                    size_t idx = (size_t)tok * DD + col;
                    out[idx]     += acc[mt][nt][half * 2]     + b2[(size_t)e * DD + col];
                    out[idx + 1] += acc[mt][nt][half * 2 + 1] + b2[(size_t)e * DD + col + 1];
                }
            }
        }
    }
}

// ---------------- launch -------------------------------------------------------
extern "C" void kernel_launch(void* const* d_in, const int* in_sizes, int n_in,
                              void* d_out, int out_size) {
    const float* x     = (const float*)d_in[0];
    const float* ln1_g = (const float*)d_in[1];
    const float* ln1_b = (const float*)d_in[2];
    const float* ln2_g = (const float*)d_in[3];
    const float* ln2_b = (const float*)d_in[4];
    const float* Wq    = (const float*)d_in[5];
    const float* Wk    = (const float*)d_in[6];
    const float* Wv    = (const float*)d_in[7];
    const float* Wp    = (const float*)d_in[8];
    const float* bp    = (const float*)d_in[9];
    const float* Wg    = (const float*)d_in[10];
    const float* W1    = (const float*)d_in[11];
    const float* b1    = (const float*)d_in[12];
    const float* W2    = (const float*)d_in[13];
    const float* b2    = (const float*)d_in[14];
    float* out = (float*)d_out;

    const int smem_g = SMEM_G_FLOATS * 4;        // 82944
    const int smem_a = ATT_SMEM_FLOATS * 4;      // 141312
    static bool attr_set = false;
    if (!attr_set) {
        cudaFuncSetAttribute(qkv_tc,  cudaFuncAttributeMaxDynamicSharedMemorySize, smem_g);
        cudaFuncSetAttribute(proj_tc, cudaFuncAttributeMaxDynamicSharedMemorySize, smem_g);
        cudaFuncSetAttribute(ffn1_tc, cudaFuncAttributeMaxDynamicSharedMemorySize, smem_g);
        cudaFuncSetAttribute(ffn2_tc, cudaFuncAttributeMaxDynamicSharedMemorySize, smem_g);
        cudaFuncSetAttribute(attn_tc, cudaFuncAttributeMaxDynamicSharedMemorySize, smem_a);
        attr_set = true;
    }

    ln_kernel<<<NN, 256>>>(x, ln1_g, ln1_b, 0);
    qkv_tc<<<dim3(NN / 128, 36), 256, smem_g>>>(Wq, Wk, Wv);
    attn_tc<<<dim3(TT / 128, HH, BB), 256, smem_a>>>();
    proj_tc<<<dim3(NN / 128, DD / 64), 256, smem_g>>>(Wp, bp, x, out);
    ln_kernel<<<NN, 256>>>(out, ln2_g, ln2_b, 1);
    moe_zero<<<1, 32>>>();
    gate_kernel<<<NN * 32 / 256, 256>>>(Wg);
    moe_scan<<<1, 1>>>();
    moe_scatter<<<NN / 256, 256>>>();
    ffn1_tc<<<dim3(NPAD / 128, DFF / 64), 256, smem_g>>>(W1, b1);
    ffn2_tc<<<dim3(NPAD / 128, DD / 64), 256, smem_g>>>(W2, b2, out);
}